// round 2
// baseline (speedup 1.0000x reference)
#include <cuda_runtime.h>
#include <cuda_bf16.h>

// Problem constants
#define BB 16
#define LL 512
#define HS 1024
#define HH 16
#define DD 64
#define MROWS (BB*LL)        // 8192

// -------------------- scratch (allocation-free) --------------------
__device__ float g_vh[BB*HH*LL*DD];   // [B,H,L,D]
__device__ float g_kh[BB*HH*LL*DD];
__device__ float g_qh[BB*HH*LL*DD];
__device__ float g_qn[BB*HH*LL*DD];   // modulated q
__device__ float g_att[BB*LL*HS];     // [B,L,H*D]

// ====================================================================
// Tiled fp32 GEMM:  C[M,N] = A[M,K] @ Bw[N,K]^T   (both K-contiguous)
// BM=BN=128, BK=16, 256 threads, 8x8 micro-tiles.
// OUTMODE 0: plain row-major C[i*N+j]
// OUTMODE 1: head layout   out[((b*16+h)*512+l)*64+d], i=b*512+l, j=h*64+d
// ====================================================================
template<int OUTMODE>
__global__ void __launch_bounds__(256) gemm_nt(const float* __restrict__ A,
                                               const float* __restrict__ Bw,
                                               float* __restrict__ C,
                                               int M, int N, int K)
{
    __shared__ float As[16][128];
    __shared__ float Bs[16][128];

    const int tid = threadIdx.x;
    const int br  = blockIdx.y;
    const int bc  = blockIdx.x;
    const int ty  = tid >> 4;      // 0..15
    const int tx  = tid & 15;      // 0..15

    const float* Ab = A  + (long)br * 128 * K;
    const float* Bb = Bw + (long)bc * 128 * K;

    float acc[8][8];
#pragma unroll
    for (int r = 0; r < 8; ++r)
#pragma unroll
        for (int c = 0; c < 8; ++c) acc[r][c] = 0.f;

    for (int k0 = 0; k0 < K; k0 += 16) {
#pragma unroll
        for (int it = 0; it < 2; ++it) {
            int qidx = tid + it * 256;       // 0..511
            int row  = qidx >> 2;            // 0..127
            int c4   = qidx & 3;             // 0..3 (float4 slot)
            float4 av = *(const float4*)(Ab + (long)row * K + k0 + c4 * 4);
            As[c4*4+0][row] = av.x; As[c4*4+1][row] = av.y;
            As[c4*4+2][row] = av.z; As[c4*4+3][row] = av.w;
            float4 bv = *(const float4*)(Bb + (long)row * K + k0 + c4 * 4);
            Bs[c4*4+0][row] = bv.x; Bs[c4*4+1][row] = bv.y;
            Bs[c4*4+2][row] = bv.z; Bs[c4*4+3][row] = bv.w;
        }
        __syncthreads();

#pragma unroll
        for (int kk = 0; kk < 16; ++kk) {
            float a[8], b[8];
#pragma unroll
            for (int r = 0; r < 8; ++r) a[r] = As[kk][ty*8 + r];
#pragma unroll
            for (int c = 0; c < 8; ++c) b[c] = Bs[kk][tx*8 + c];
#pragma unroll
            for (int r = 0; r < 8; ++r)
#pragma unroll
                for (int c = 0; c < 8; ++c)
                    acc[r][c] = fmaf(a[r], b[c], acc[r][c]);
        }
        __syncthreads();
    }

    const int i0 = br * 128 + ty * 8;
    const int j0 = bc * 128 + tx * 8;
#pragma unroll
    for (int r = 0; r < 8; ++r) {
#pragma unroll
        for (int c = 0; c < 8; ++c) {
            int i = i0 + r, j = j0 + c;
            if (OUTMODE == 0) {
                C[(long)i * N + j] = acc[r][c];
            } else {
                int b = i >> 9, l = i & 511;
                int h = j >> 6, d = j & 63;
                C[(((long)(b*16 + h) * 512) + l) * 64 + d] = acc[r][c];
            }
        }
    }
}

// ====================================================================
// Flash-style attention, 64 q-rows per block, 64-wide KV tiles.
// Q is always [B,H,L,D] contiguous. K/V/Out addressed via strides.
// Out = softmax(mask(Q K^T * 0.125)) V  (+ Q if residual)
// Mask is read as 4-byte elements (int32 or float32): nonzero = masked.
// ====================================================================
__global__ void __launch_bounds__(256) attn_kernel(
    const float* __restrict__ Q,
    const float* __restrict__ Kb, long kBS, long kHS, int kRS,
    const float* __restrict__ Vb, long vBS, long vHS, int vRS,
    const unsigned int* __restrict__ mask,
    float* __restrict__ Ob, long oBS, long oHS, int oRS,
    int residual)
{
    extern __shared__ float sm[];
    float* Qs  = sm;                 // 64*65
    float* Ks  = Qs + 64 * 65;
    float* Vs  = Ks + 64 * 65;
    float* Ss  = Vs + 64 * 65;
    float* m_s = Ss + 64 * 65;       // 64
    float* l_s = m_s + 64;
    float* al_s = l_s + 64;
    unsigned char* Ms = (unsigned char*)(al_s + 64);   // 64*64 bytes

    const int b  = blockIdx.z;
    const int h  = blockIdx.y;
    const int q0 = blockIdx.x * 64;

    const float* Qp = Q + (((long)(b*16 + h) * 512) + q0) * 64;
    const float* Kp = Kb + (long)b * kBS + (long)h * kHS;
    const float* Vp = Vb + (long)b * vBS + (long)h * vHS;
    const unsigned int* Mp = mask + (long)b * LL * LL + (long)q0 * LL;
    float* Op = Ob + (long)b * oBS + (long)h * oHS + (long)q0 * oRS;

    const int tid = threadIdx.x;
    const int ty  = tid >> 4;     // 0..15
    const int tx  = tid & 15;     // 0..15

    // load Q tile (contiguous 4096 floats)
#pragma unroll
    for (int it = 0; it < 4; ++it) {
        int f   = tid + it * 256;     // 0..1023 float4
        int row = f >> 4, c4 = f & 15;
        float4 v = *(const float4*)(Qp + (long)row * 64 + c4 * 4);
        float* dst = Qs + row * 65 + c4 * 4;
        dst[0] = v.x; dst[1] = v.y; dst[2] = v.z; dst[3] = v.w;
    }
    if (tid < 64) { m_s[tid] = -1e30f; l_s[tid] = 0.f; }

    float o[4][4];
#pragma unroll
    for (int r = 0; r < 4; ++r)
#pragma unroll
        for (int c = 0; c < 4; ++c) o[r][c] = 0.f;

    __syncthreads();

    for (int kt = 0; kt < 8; ++kt) {
        const int k0 = kt * 64;
        // load K and V tiles
#pragma unroll
        for (int it = 0; it < 4; ++it) {
            int f   = tid + it * 256;
            int row = f >> 4, c4 = f & 15;
            float4 kv = *(const float4*)(Kp + (long)(k0 + row) * kRS + c4 * 4);
            float* d1 = Ks + row * 65 + c4 * 4;
            d1[0] = kv.x; d1[1] = kv.y; d1[2] = kv.z; d1[3] = kv.w;
            float4 vv = *(const float4*)(Vp + (long)(k0 + row) * vRS + c4 * 4);
            float* d2 = Vs + row * 65 + c4 * 4;
            d2[0] = vv.x; d2[1] = vv.y; d2[2] = vv.z; d2[3] = vv.w;
        }
        // load mask tile: 64x64 4-byte elements -> pack to bytes (nonzero = masked)
#pragma unroll
        for (int it = 0; it < 4; ++it) {
            int u   = tid + it * 256;       // 0..1023, 4 elements each
            int row = u >> 4, c4 = u & 15;
            uint4 m4 = *(const uint4*)(Mp + (long)row * LL + k0 + c4 * 4);
            uchar4 pk;
            pk.x = m4.x ? 1 : 0;
            pk.y = m4.y ? 1 : 0;
            pk.z = m4.z ? 1 : 0;
            pk.w = m4.w ? 1 : 0;
            ((uchar4*)Ms)[row * 16 + c4] = pk;
        }
        __syncthreads();

        // S = Q K^T (4x4 micro-tile per thread)
        float s[4][4];
#pragma unroll
        for (int r = 0; r < 4; ++r)
#pragma unroll
            for (int c = 0; c < 4; ++c) s[r][c] = 0.f;

        for (int kk = 0; kk < 64; ++kk) {
            float a[4], bb[4];
#pragma unroll
            for (int r = 0; r < 4; ++r) a[r]  = Qs[(ty*4 + r) * 65 + kk];
#pragma unroll
            for (int c = 0; c < 4; ++c) bb[c] = Ks[(tx*4 + c) * 65 + kk];
#pragma unroll
            for (int r = 0; r < 4; ++r)
#pragma unroll
                for (int c = 0; c < 4; ++c)
                    s[r][c] = fmaf(a[r], bb[c], s[r][c]);
        }

        // scale, mask, stash to smem
#pragma unroll
        for (int r = 0; r < 4; ++r) {
#pragma unroll
            for (int c = 0; c < 4; ++c) {
                int rr = ty*4 + r, cc = tx*4 + c;
                float val = s[r][c] * 0.125f;
                if (Ms[rr * 64 + cc]) val = -1e9f;
                Ss[rr * 65 + cc] = val;
            }
        }
        __syncthreads();

        // row max (4 lanes per row)
        {
            int row = tid >> 2, seg = tid & 3;
            const float* base = Ss + row * 65 + seg * 16;
            float mx = -3.0e38f;
#pragma unroll
            for (int i = 0; i < 16; ++i) mx = fmaxf(mx, base[i]);
            mx = fmaxf(mx, __shfl_xor_sync(0xffffffffu, mx, 1));
            mx = fmaxf(mx, __shfl_xor_sync(0xffffffffu, mx, 2));
            if (seg == 0) {
                float mo = m_s[row];
                float mn = fmaxf(mo, mx);
                m_s[row]  = mn;
                al_s[row] = __expf(mo - mn);
            }
        }
        __syncthreads();

        // exp + row sum
        {
            int row = tid >> 2, seg = tid & 3;
            float mn = m_s[row];
            float* base = Ss + row * 65 + seg * 16;
            float sum = 0.f;
#pragma unroll
            for (int i = 0; i < 16; ++i) {
                float e = __expf(base[i] - mn);
                base[i] = e;
                sum += e;
            }
            sum += __shfl_xor_sync(0xffffffffu, sum, 1);
            sum += __shfl_xor_sync(0xffffffffu, sum, 2);
            if (seg == 0) l_s[row] = l_s[row] * al_s[row] + sum;
        }
        __syncthreads();

        // rescale O, then O += P V
        float alr[4];
#pragma unroll
        for (int r = 0; r < 4; ++r) alr[r] = al_s[ty*4 + r];
#pragma unroll
        for (int r = 0; r < 4; ++r)
#pragma unroll
            for (int c = 0; c < 4; ++c) o[r][c] *= alr[r];

        for (int j = 0; j < 64; ++j) {
            float p[4], vv[4];
#pragma unroll
            for (int r = 0; r < 4; ++r) p[r]  = Ss[(ty*4 + r) * 65 + j];
#pragma unroll
            for (int c = 0; c < 4; ++c) vv[c] = Vs[j * 65 + tx*4 + c];
#pragma unroll
            for (int r = 0; r < 4; ++r)
#pragma unroll
                for (int c = 0; c < 4; ++c)
                    o[r][c] = fmaf(p[r], vv[c], o[r][c]);
        }
        __syncthreads();
    }

    // finalize: divide by l, optional residual, store
#pragma unroll
    for (int r = 0; r < 4; ++r) {
        int rr = ty*4 + r;
        float inv = 1.0f / l_s[rr];
#pragma unroll
        for (int c = 0; c < 4; ++c) {
            int cc = tx*4 + c;
            float val = o[r][c] * inv;
            if (residual) val += Qs[rr * 65 + cc];
            Op[(long)rr * oRS + cc] = val;
        }
    }
}

// ====================================================================
extern "C" void kernel_launch(void* const* d_in, const int* in_sizes, int n_in,
                              void* d_out, int out_size)
{
    (void)in_sizes; (void)n_in; (void)out_size;
    const float* v   = (const float*)d_in[0];
    const float* k   = (const float*)d_in[1];
    const float* q   = (const float*)d_in[2];
    const float* img = (const float*)d_in[3];
    const float* Wv  = (const float*)d_in[4];
    const float* Wk  = (const float*)d_in[5];
    const float* Wq  = (const float*)d_in[6];
    const float* Wm  = (const float*)d_in[7];
    const unsigned int* absm = (const unsigned int*)d_in[8];
    const unsigned int* mask = (const unsigned int*)d_in[9];
    float* out = (float*)d_out;

    float *vh, *kh, *qh, *qn, *att;
    cudaGetSymbolAddress((void**)&vh,  g_vh);
    cudaGetSymbolAddress((void**)&kh,  g_kh);
    cudaGetSymbolAddress((void**)&qh,  g_qh);
    cudaGetSymbolAddress((void**)&qn,  g_qn);
    cudaGetSymbolAddress((void**)&att, g_att);

    dim3 gg(HS / 128, MROWS / 128);   // (8, 64)
    gemm_nt<1><<<gg, 256>>>(v, Wv, vh, MROWS, HS, HS);
    gemm_nt<1><<<gg, 256>>>(k, Wk, kh, MROWS, HS, HS);
    gemm_nt<1><<<gg, 256>>>(q, Wq, qh, MROWS, HS, HS);

    const size_t smem = (4 * 64 * 65 + 3 * 64) * sizeof(float) + 64 * 64;
    cudaFuncSetAttribute(attn_kernel,
                         cudaFuncAttributeMaxDynamicSharedMemorySize, (int)smem);

    dim3 ga(LL / 64, HH, BB);   // (8, 16, 16)
    // Stage 1: modulate — K=V=img_abs (strided heads), residual add, out -> g_qn [B,H,L,D]
    attn_kernel<<<ga, 256, smem>>>(
        qh,
        img, (long)LL * HS, 64L, HS,
        img, (long)LL * HS, 64L, HS,
        absm,
        qn,  (long)HH * LL * DD, (long)LL * DD, DD,
        1);
    // Stage 2: main attention — K=kh, V=vh, out -> g_att [B,L,H*D]
    attn_kernel<<<ga, 256, smem>>>(
        qn,
        kh, (long)HH * LL * DD, (long)LL * DD, DD,
        vh, (long)HH * LL * DD, (long)LL * DD, DD,
        mask,
        att, (long)LL * HS, 64L, HS,
        0);

    gemm_nt<0><<<gg, 256>>>(att, Wm, out, MROWS, HS, HS);
}

// round 3
// speedup vs baseline: 1.3092x; 1.3092x over previous
#include <cuda_runtime.h>
#include <cuda_bf16.h>

// Problem constants
#define BB 16
#define LL 512
#define HS 1024
#define HH 16
#define DD 64
#define MROWS (BB*LL)        // 8192

// -------------------- scratch (allocation-free) --------------------
__device__ float g_vh[BB*HH*LL*DD];   // [B,H,L,D]
__device__ float g_kh[BB*HH*LL*DD];
__device__ float g_qh[BB*HH*LL*DD];
__device__ float g_qn[BB*HH*LL*DD];   // modulated q
__device__ float g_att[BB*LL*HS];     // [B,L,H*D]

// ------------------ tf32 helpers ------------------
__device__ __forceinline__ unsigned f2tf32(float x) {
    unsigned r;
    asm("cvt.rna.tf32.f32 %0, %1;" : "=r"(r) : "f"(x));
    return r;
}

__device__ __forceinline__ void mma_tf32(float d[4],
                                         unsigned a0, unsigned a1, unsigned a2, unsigned a3,
                                         unsigned b0, unsigned b1)
{
    asm volatile(
        "mma.sync.aligned.m16n8k8.row.col.f32.tf32.tf32.f32 "
        "{%0,%1,%2,%3}, {%4,%5,%6,%7}, {%8,%9}, {%0,%1,%2,%3};\n"
        : "+f"(d[0]), "+f"(d[1]), "+f"(d[2]), "+f"(d[3])
        : "r"(a0), "r"(a1), "r"(a2), "r"(a3), "r"(b0), "r"(b1));
}

// ====================================================================
// tf32 tensor-core GEMM with 3-term compensation:
//   C[M,N] = A[M,K] @ Bw[N,K]^T   (both K-contiguous, fp32 in/out)
// Block tile 128x128, BK=32, 256 threads (8 warps, 2x4), warp tile 64x32.
// Each warp: 4 M-subtiles (m16) x 4 N-subtiles (n8), mma.m16n8k8.
// smem holds tf32-hi and tf32-lo copies of A and B tiles (pitch 36).
// OUTMODE 0: row-major C[i*N+j]
// OUTMODE 1: head layout out[((b*16+h)*512+l)*64+d], i=b*512+l, j=h*64+d
// ====================================================================
#define GPITCH 36   // 32 + 4 pad floats; 36*4=144 bytes (16B aligned rows)

template<int OUTMODE>
__global__ void __launch_bounds__(256, 1) gemm_tf32(const float* __restrict__ A,
                                                    const float* __restrict__ Bw,
                                                    float* __restrict__ C,
                                                    int M, int N, int K)
{
    extern __shared__ float smem[];
    float* AsHi = smem;                    // 128*36
    float* AsLo = AsHi + 128 * GPITCH;
    float* BsHi = AsLo + 128 * GPITCH;
    float* BsLo = BsHi + 128 * GPITCH;

    const int tid  = threadIdx.x;
    const int br   = blockIdx.y;
    const int bc   = blockIdx.x;
    const int wid  = tid >> 5;
    const int lane = tid & 31;
    const int g    = lane >> 2;    // group id 0..7
    const int tig  = lane & 3;     // thread in group 0..3

    const int wm = wid >> 2;       // 0..1 : warp row  (64 rows)
    const int wn = wid & 3;        // 0..3 : warp col  (32 cols)

    const float* Ab = A  + (long)br * 128 * K;
    const float* Bb = Bw + (long)bc * 128 * K;

    // accumulators: 4 m-subtiles x 4 n-subtiles x 4 regs
    float acc[4][4][4];
#pragma unroll
    for (int mt = 0; mt < 4; ++mt)
#pragma unroll
        for (int nt = 0; nt < 4; ++nt)
#pragma unroll
            for (int r = 0; r < 4; ++r) acc[mt][nt][r] = 0.f;

    // g2s decomposition: 1024 float4 per operand tile, 4 per thread
    const int ldrow = tid >> 3;          // 0..31 base row (advance by 32)
    const int ldkq  = tid & 7;           // float4 slot in k (0..7)

    // ---- helper lambdas (inlined) ----
    auto store_tile = [&](const float4* av, const float4* bv) {
#pragma unroll
        for (int it = 0; it < 4; ++it) {
            int row = ldrow + it * 32;
            float4 a = av[it];
            float4 hi, lo;
            hi.x = __uint_as_float(f2tf32(a.x)); lo.x = __uint_as_float(f2tf32(a.x - hi.x));
            hi.y = __uint_as_float(f2tf32(a.y)); lo.y = __uint_as_float(f2tf32(a.y - hi.y));
            hi.z = __uint_as_float(f2tf32(a.z)); lo.z = __uint_as_float(f2tf32(a.z - hi.z));
            hi.w = __uint_as_float(f2tf32(a.w)); lo.w = __uint_as_float(f2tf32(a.w - hi.w));
            *(float4*)(AsHi + row * GPITCH + ldkq * 4) = hi;
            *(float4*)(AsLo + row * GPITCH + ldkq * 4) = lo;
            float4 b = bv[it];
            hi.x = __uint_as_float(f2tf32(b.x)); lo.x = __uint_as_float(f2tf32(b.x - hi.x));
            hi.y = __uint_as_float(f2tf32(b.y)); lo.y = __uint_as_float(f2tf32(b.y - hi.y));
            hi.z = __uint_as_float(f2tf32(b.z)); lo.z = __uint_as_float(f2tf32(b.z - hi.z));
            hi.w = __uint_as_float(f2tf32(b.w)); lo.w = __uint_as_float(f2tf32(b.w - hi.w));
            *(float4*)(BsHi + row * GPITCH + ldkq * 4) = hi;
            *(float4*)(BsLo + row * GPITCH + ldkq * 4) = lo;
        }
    };

    float4 pfA[4], pfB[4];

    // preload k-tile 0
#pragma unroll
    for (int it = 0; it < 4; ++it) {
        int row = ldrow + it * 32;
        pfA[it] = *(const float4*)(Ab + (long)row * K + ldkq * 4);
        pfB[it] = *(const float4*)(Bb + (long)row * K + ldkq * 4);
    }
    store_tile(pfA, pfB);
    __syncthreads();

    const int nKt = K / 32;
    for (int kt = 0; kt < nKt; ++kt) {
        // prefetch next tile into registers
        if (kt + 1 < nKt) {
            int k0 = (kt + 1) * 32;
#pragma unroll
            for (int it = 0; it < 4; ++it) {
                int row = ldrow + it * 32;
                pfA[it] = *(const float4*)(Ab + (long)row * K + k0 + ldkq * 4);
                pfB[it] = *(const float4*)(Bb + (long)row * K + k0 + ldkq * 4);
            }
        }

        // compute: 4 k-steps of 8
#pragma unroll
        for (int ks = 0; ks < 4; ++ks) {
            const int kk = ks * 8;
            unsigned ah[4][4], al[4][4];
#pragma unroll
            for (int mt = 0; mt < 4; ++mt) {
                int m = wm * 64 + mt * 16 + g;
                const float* pH = AsHi + m * GPITCH + kk + tig;
                const float* pL = AsLo + m * GPITCH + kk + tig;
                ah[mt][0] = __float_as_uint(pH[0]);
                ah[mt][2] = __float_as_uint(pH[4]);
                ah[mt][1] = __float_as_uint(pH[8 * GPITCH]);
                ah[mt][3] = __float_as_uint(pH[8 * GPITCH + 4]);
                al[mt][0] = __float_as_uint(pL[0]);
                al[mt][2] = __float_as_uint(pL[4]);
                al[mt][1] = __float_as_uint(pL[8 * GPITCH]);
                al[mt][3] = __float_as_uint(pL[8 * GPITCH + 4]);
            }
            unsigned bh[4][2], bl[4][2];
#pragma unroll
            for (int nt = 0; nt < 4; ++nt) {
                int n = wn * 32 + nt * 8 + g;
                const float* pH = BsHi + n * GPITCH + kk + tig;
                const float* pL = BsLo + n * GPITCH + kk + tig;
                bh[nt][0] = __float_as_uint(pH[0]);
                bh[nt][1] = __float_as_uint(pH[4]);
                bl[nt][0] = __float_as_uint(pL[0]);
                bl[nt][1] = __float_as_uint(pL[4]);
            }
#pragma unroll
            for (int mt = 0; mt < 4; ++mt) {
#pragma unroll
                for (int nt = 0; nt < 4; ++nt) {
                    mma_tf32(acc[mt][nt], ah[mt][0], ah[mt][1], ah[mt][2], ah[mt][3],
                             bh[nt][0], bh[nt][1]);
                    mma_tf32(acc[mt][nt], al[mt][0], al[mt][1], al[mt][2], al[mt][3],
                             bh[nt][0], bh[nt][1]);
                    mma_tf32(acc[mt][nt], ah[mt][0], ah[mt][1], ah[mt][2], ah[mt][3],
                             bl[nt][0], bl[nt][1]);
                }
            }
        }
        __syncthreads();
        if (kt + 1 < nKt) {
            store_tile(pfA, pfB);
        }
        __syncthreads();
    }

    // epilogue: c0/c1 adjacent cols -> float2 stores
#pragma unroll
    for (int mt = 0; mt < 4; ++mt) {
#pragma unroll
        for (int nt = 0; nt < 4; ++nt) {
            int jj = bc * 128 + wn * 32 + nt * 8 + tig * 2;
#pragma unroll
            for (int half = 0; half < 2; ++half) {
                int ii = br * 128 + wm * 64 + mt * 16 + g + half * 8;
                float2 val;
                val.x = acc[mt][nt][half * 2 + 0];
                val.y = acc[mt][nt][half * 2 + 1];
                if (OUTMODE == 0) {
                    *(float2*)(C + (long)ii * N + jj) = val;
                } else {
                    int b = ii >> 9, l = ii & 511;
                    int h = jj >> 6, d = jj & 63;
                    *(float2*)(C + (((long)(b * 16 + h) * 512) + l) * 64 + d) = val;
                }
            }
        }
    }
}

// ====================================================================
// Flash-style attention, 64 q-rows per block, 64-wide KV tiles.
// Q is always [B,H,L,D] contiguous. K/V/Out addressed via strides.
// Out = softmax(mask(Q K^T * 0.125)) V  (+ Q if residual)
// Mask is read as 4-byte elements (int32 or float32): nonzero = masked.
// ====================================================================
__global__ void __launch_bounds__(256) attn_kernel(
    const float* __restrict__ Q,
    const float* __restrict__ Kb, long kBS, long kHS, int kRS,
    const float* __restrict__ Vb, long vBS, long vHS, int vRS,
    const unsigned int* __restrict__ mask,
    float* __restrict__ Ob, long oBS, long oHS, int oRS,
    int residual)
{
    extern __shared__ float sm[];
    float* Qs  = sm;                 // 64*65
    float* Ks  = Qs + 64 * 65;
    float* Vs  = Ks + 64 * 65;
    float* Ss  = Vs + 64 * 65;
    float* m_s = Ss + 64 * 65;       // 64
    float* l_s = m_s + 64;
    float* al_s = l_s + 64;
    unsigned char* Ms = (unsigned char*)(al_s + 64);   // 64*64 bytes

    const int b  = blockIdx.z;
    const int h  = blockIdx.y;
    const int q0 = blockIdx.x * 64;

    const float* Qp = Q + (((long)(b*16 + h) * 512) + q0) * 64;
    const float* Kp = Kb + (long)b * kBS + (long)h * kHS;
    const float* Vp = Vb + (long)b * vBS + (long)h * vHS;
    const unsigned int* Mp = mask + (long)b * LL * LL + (long)q0 * LL;
    float* Op = Ob + (long)b * oBS + (long)h * oHS + (long)q0 * oRS;

    const int tid = threadIdx.x;
    const int ty  = tid >> 4;     // 0..15
    const int tx  = tid & 15;     // 0..15

    // load Q tile (contiguous 4096 floats)
#pragma unroll
    for (int it = 0; it < 4; ++it) {
        int f   = tid + it * 256;     // 0..1023 float4
        int row = f >> 4, c4 = f & 15;
        float4 v = *(const float4*)(Qp + (long)row * 64 + c4 * 4);
        float* dst = Qs + row * 65 + c4 * 4;
        dst[0] = v.x; dst[1] = v.y; dst[2] = v.z; dst[3] = v.w;
    }
    if (tid < 64) { m_s[tid] = -1e30f; l_s[tid] = 0.f; }

    float o[4][4];
#pragma unroll
    for (int r = 0; r < 4; ++r)
#pragma unroll
        for (int c = 0; c < 4; ++c) o[r][c] = 0.f;

    __syncthreads();

    for (int kt = 0; kt < 8; ++kt) {
        const int k0 = kt * 64;
        // load K and V tiles
#pragma unroll
        for (int it = 0; it < 4; ++it) {
            int f   = tid + it * 256;
            int row = f >> 4, c4 = f & 15;
            float4 kv = *(const float4*)(Kp + (long)(k0 + row) * kRS + c4 * 4);
            float* d1 = Ks + row * 65 + c4 * 4;
            d1[0] = kv.x; d1[1] = kv.y; d1[2] = kv.z; d1[3] = kv.w;
            float4 vv = *(const float4*)(Vp + (long)(k0 + row) * vRS + c4 * 4);
            float* d2 = Vs + row * 65 + c4 * 4;
            d2[0] = vv.x; d2[1] = vv.y; d2[2] = vv.z; d2[3] = vv.w;
        }
        // load mask tile: 64x64 4-byte elements -> pack to bytes (nonzero = masked)
#pragma unroll
        for (int it = 0; it < 4; ++it) {
            int u   = tid + it * 256;       // 0..1023, 4 elements each
            int row = u >> 4, c4 = u & 15;
            uint4 m4 = *(const uint4*)(Mp + (long)row * LL + k0 + c4 * 4);
            uchar4 pk;
            pk.x = m4.x ? 1 : 0;
            pk.y = m4.y ? 1 : 0;
            pk.z = m4.z ? 1 : 0;
            pk.w = m4.w ? 1 : 0;
            ((uchar4*)Ms)[row * 16 + c4] = pk;
        }
        __syncthreads();

        // S = Q K^T (4x4 micro-tile per thread)
        float s[4][4];
#pragma unroll
        for (int r = 0; r < 4; ++r)
#pragma unroll
            for (int c = 0; c < 4; ++c) s[r][c] = 0.f;

        for (int kk = 0; kk < 64; ++kk) {
            float a[4], bb[4];
#pragma unroll
            for (int r = 0; r < 4; ++r) a[r]  = Qs[(ty*4 + r) * 65 + kk];
#pragma unroll
            for (int c = 0; c < 4; ++c) bb[c] = Ks[(tx*4 + c) * 65 + kk];
#pragma unroll
            for (int r = 0; r < 4; ++r)
#pragma unroll
                for (int c = 0; c < 4; ++c)
                    s[r][c] = fmaf(a[r], bb[c], s[r][c]);
        }

        // scale, mask, stash to smem
#pragma unroll
        for (int r = 0; r < 4; ++r) {
#pragma unroll
            for (int c = 0; c < 4; ++c) {
                int rr = ty*4 + r, cc = tx*4 + c;
                float val = s[r][c] * 0.125f;
                if (Ms[rr * 64 + cc]) val = -1e9f;
                Ss[rr * 65 + cc] = val;
            }
        }
        __syncthreads();

        // row max (4 lanes per row)
        {
            int row = tid >> 2, seg = tid & 3;
            const float* base = Ss + row * 65 + seg * 16;
            float mx = -3.0e38f;
#pragma unroll
            for (int i = 0; i < 16; ++i) mx = fmaxf(mx, base[i]);
            mx = fmaxf(mx, __shfl_xor_sync(0xffffffffu, mx, 1));
            mx = fmaxf(mx, __shfl_xor_sync(0xffffffffu, mx, 2));
            if (seg == 0) {
                float mo = m_s[row];
                float mn = fmaxf(mo, mx);
                m_s[row]  = mn;
                al_s[row] = __expf(mo - mn);
            }
        }
        __syncthreads();

        // exp + row sum
        {
            int row = tid >> 2, seg = tid & 3;
            float mn = m_s[row];
            float* base = Ss + row * 65 + seg * 16;
            float sum = 0.f;
#pragma unroll
            for (int i = 0; i < 16; ++i) {
                float e = __expf(base[i] - mn);
                base[i] = e;
                sum += e;
            }
            sum += __shfl_xor_sync(0xffffffffu, sum, 1);
            sum += __shfl_xor_sync(0xffffffffu, sum, 2);
            if (seg == 0) l_s[row] = l_s[row] * al_s[row] + sum;
        }
        __syncthreads();

        // rescale O, then O += P V
        float alr[4];
#pragma unroll
        for (int r = 0; r < 4; ++r) alr[r] = al_s[ty*4 + r];
#pragma unroll
        for (int r = 0; r < 4; ++r)
#pragma unroll
            for (int c = 0; c < 4; ++c) o[r][c] *= alr[r];

        for (int j = 0; j < 64; ++j) {
            float p[4], vv[4];
#pragma unroll
            for (int r = 0; r < 4; ++r) p[r]  = Ss[(ty*4 + r) * 65 + j];
#pragma unroll
            for (int c = 0; c < 4; ++c) vv[c] = Vs[j * 65 + tx*4 + c];
#pragma unroll
            for (int r = 0; r < 4; ++r)
#pragma unroll
                for (int c = 0; c < 4; ++c)
                    o[r][c] = fmaf(p[r], vv[c], o[r][c]);
        }
        __syncthreads();
    }

    // finalize: divide by l, optional residual, store
#pragma unroll
    for (int r = 0; r < 4; ++r) {
        int rr = ty*4 + r;
        float inv = 1.0f / l_s[rr];
#pragma unroll
        for (int c = 0; c < 4; ++c) {
            int cc = tx*4 + c;
            float val = o[r][c] * inv;
            if (residual) val += Qs[rr * 65 + cc];
            Op[(long)rr * oRS + cc] = val;
        }
    }
}

// ====================================================================
extern "C" void kernel_launch(void* const* d_in, const int* in_sizes, int n_in,
                              void* d_out, int out_size)
{
    (void)in_sizes; (void)n_in; (void)out_size;
    const float* v   = (const float*)d_in[0];
    const float* k   = (const float*)d_in[1];
    const float* q   = (const float*)d_in[2];
    const float* img = (const float*)d_in[3];
    const float* Wv  = (const float*)d_in[4];
    const float* Wk  = (const float*)d_in[5];
    const float* Wq  = (const float*)d_in[6];
    const float* Wm  = (const float*)d_in[7];
    const unsigned int* absm = (const unsigned int*)d_in[8];
    const unsigned int* mask = (const unsigned int*)d_in[9];
    float* out = (float*)d_out;

    float *vh, *kh, *qh, *qn, *att;
    cudaGetSymbolAddress((void**)&vh,  g_vh);
    cudaGetSymbolAddress((void**)&kh,  g_kh);
    cudaGetSymbolAddress((void**)&qh,  g_qh);
    cudaGetSymbolAddress((void**)&qn,  g_qn);
    cudaGetSymbolAddress((void**)&att, g_att);

    const int gsmem = 4 * 128 * GPITCH * sizeof(float);   // 73728
    cudaFuncSetAttribute(gemm_tf32<0>,
                         cudaFuncAttributeMaxDynamicSharedMemorySize, gsmem);
    cudaFuncSetAttribute(gemm_tf32<1>,
                         cudaFuncAttributeMaxDynamicSharedMemorySize, gsmem);

    dim3 gg(HS / 128, MROWS / 128);   // (8, 64)
    gemm_tf32<1><<<gg, 256, gsmem>>>(v, Wv, vh, MROWS, HS, HS);
    gemm_tf32<1><<<gg, 256, gsmem>>>(k, Wk, kh, MROWS, HS, HS);
    gemm_tf32<1><<<gg, 256, gsmem>>>(q, Wq, qh, MROWS, HS, HS);

    const size_t smem = (4 * 64 * 65 + 3 * 64) * sizeof(float) + 64 * 64;
    cudaFuncSetAttribute(attn_kernel,
                         cudaFuncAttributeMaxDynamicSharedMemorySize, (int)smem);

    dim3 ga(LL / 64, HH, BB);   // (8, 16, 16)
    // Stage 1: modulate — K=V=img_abs (strided heads), residual add, out -> g_qn [B,H,L,D]
    attn_kernel<<<ga, 256, smem>>>(
        qh,
        img, (long)LL * HS, 64L, HS,
        img, (long)LL * HS, 64L, HS,
        absm,
        qn,  (long)HH * LL * DD, (long)LL * DD, DD,
        1);
    // Stage 2: main attention — K=kh, V=vh, out -> g_att [B,L,H*D]
    attn_kernel<<<ga, 256, smem>>>(
        qn,
        kh, (long)HH * LL * DD, (long)LL * DD, DD,
        vh, (long)HH * LL * DD, (long)LL * DD, DD,
        mask,
        att, (long)LL * HS, 64L, HS,
        0);

    gemm_tf32<0><<<gg, 256, gsmem>>>(att, Wm, out, MROWS, HS, HS);
}

// round 4
// speedup vs baseline: 1.6417x; 1.2540x over previous
#include <cuda_runtime.h>
#include <cuda_bf16.h>

// Problem constants
#define BB 16
#define LL 512
#define HS 1024
#define HH 16
#define DD 64
#define MROWS (BB*LL)        // 8192

// -------------------- scratch (allocation-free) --------------------
__device__ float g_vh[BB*HH*LL*DD];   // [B,H,L,D]
__device__ float g_kh[BB*HH*LL*DD];
__device__ float g_qh[BB*HH*LL*DD];
__device__ float g_qn[BB*HH*LL*DD];   // modulated q
__device__ float g_att[BB*LL*HS];     // [B,L,H*D]

// ------------------ tf32 helpers ------------------
__device__ __forceinline__ unsigned f2tf32(float x) {
    unsigned r;
    asm("cvt.rna.tf32.f32 %0, %1;" : "=r"(r) : "f"(x));
    return r;
}

__device__ __forceinline__ void split_tf32(float x, unsigned &hi, unsigned &lo) {
    hi = f2tf32(x);
    lo = f2tf32(x - __uint_as_float(hi));
}

__device__ __forceinline__ void mma_tf32(float d[4],
                                         unsigned a0, unsigned a1, unsigned a2, unsigned a3,
                                         unsigned b0, unsigned b1)
{
    asm volatile(
        "mma.sync.aligned.m16n8k8.row.col.f32.tf32.tf32.f32 "
        "{%0,%1,%2,%3}, {%4,%5,%6,%7}, {%8,%9}, {%0,%1,%2,%3};\n"
        : "+f"(d[0]), "+f"(d[1]), "+f"(d[2]), "+f"(d[3])
        : "r"(a0), "r"(a1), "r"(a2), "r"(a3), "r"(b0), "r"(b1));
}

// ====================================================================
// tf32 tensor-core GEMM with 3-term compensation (unchanged from R3)
// ====================================================================
#define GPITCH 36

template<int OUTMODE>
__global__ void __launch_bounds__(256, 1) gemm_tf32(const float* __restrict__ A,
                                                    const float* __restrict__ Bw,
                                                    float* __restrict__ C,
                                                    int M, int N, int K)
{
    extern __shared__ float smem[];
    float* AsHi = smem;                    // 128*36
    float* AsLo = AsHi + 128 * GPITCH;
    float* BsHi = AsLo + 128 * GPITCH;
    float* BsLo = BsHi + 128 * GPITCH;

    const int tid  = threadIdx.x;
    const int br   = blockIdx.y;
    const int bc   = blockIdx.x;
    const int wid  = tid >> 5;
    const int lane = tid & 31;
    const int g    = lane >> 2;
    const int tig  = lane & 3;

    const int wm = wid >> 2;
    const int wn = wid & 3;

    const float* Ab = A  + (long)br * 128 * K;
    const float* Bb = Bw + (long)bc * 128 * K;

    float acc[4][4][4];
#pragma unroll
    for (int mt = 0; mt < 4; ++mt)
#pragma unroll
        for (int nt = 0; nt < 4; ++nt)
#pragma unroll
            for (int r = 0; r < 4; ++r) acc[mt][nt][r] = 0.f;

    const int ldrow = tid >> 3;
    const int ldkq  = tid & 7;

    auto store_tile = [&](const float4* av, const float4* bv) {
#pragma unroll
        for (int it = 0; it < 4; ++it) {
            int row = ldrow + it * 32;
            float4 a = av[it];
            float4 hi, lo;
            hi.x = __uint_as_float(f2tf32(a.x)); lo.x = __uint_as_float(f2tf32(a.x - hi.x));
            hi.y = __uint_as_float(f2tf32(a.y)); lo.y = __uint_as_float(f2tf32(a.y - hi.y));
            hi.z = __uint_as_float(f2tf32(a.z)); lo.z = __uint_as_float(f2tf32(a.z - hi.z));
            hi.w = __uint_as_float(f2tf32(a.w)); lo.w = __uint_as_float(f2tf32(a.w - hi.w));
            *(float4*)(AsHi + row * GPITCH + ldkq * 4) = hi;
            *(float4*)(AsLo + row * GPITCH + ldkq * 4) = lo;
            float4 b = bv[it];
            hi.x = __uint_as_float(f2tf32(b.x)); lo.x = __uint_as_float(f2tf32(b.x - hi.x));
            hi.y = __uint_as_float(f2tf32(b.y)); lo.y = __uint_as_float(f2tf32(b.y - hi.y));
            hi.z = __uint_as_float(f2tf32(b.z)); lo.z = __uint_as_float(f2tf32(b.z - hi.z));
            hi.w = __uint_as_float(f2tf32(b.w)); lo.w = __uint_as_float(f2tf32(b.w - hi.w));
            *(float4*)(BsHi + row * GPITCH + ldkq * 4) = hi;
            *(float4*)(BsLo + row * GPITCH + ldkq * 4) = lo;
        }
    };

    float4 pfA[4], pfB[4];
#pragma unroll
    for (int it = 0; it < 4; ++it) {
        int row = ldrow + it * 32;
        pfA[it] = *(const float4*)(Ab + (long)row * K + ldkq * 4);
        pfB[it] = *(const float4*)(Bb + (long)row * K + ldkq * 4);
    }
    store_tile(pfA, pfB);
    __syncthreads();

    const int nKt = K / 32;
    for (int kt = 0; kt < nKt; ++kt) {
        if (kt + 1 < nKt) {
            int k0 = (kt + 1) * 32;
#pragma unroll
            for (int it = 0; it < 4; ++it) {
                int row = ldrow + it * 32;
                pfA[it] = *(const float4*)(Ab + (long)row * K + k0 + ldkq * 4);
                pfB[it] = *(const float4*)(Bb + (long)row * K + k0 + ldkq * 4);
            }
        }

#pragma unroll
        for (int ks = 0; ks < 4; ++ks) {
            const int kk = ks * 8;
            unsigned ah[4][4], al[4][4];
#pragma unroll
            for (int mt = 0; mt < 4; ++mt) {
                int m = wm * 64 + mt * 16 + g;
                const float* pH = AsHi + m * GPITCH + kk + tig;
                const float* pL = AsLo + m * GPITCH + kk + tig;
                ah[mt][0] = __float_as_uint(pH[0]);
                ah[mt][2] = __float_as_uint(pH[4]);
                ah[mt][1] = __float_as_uint(pH[8 * GPITCH]);
                ah[mt][3] = __float_as_uint(pH[8 * GPITCH + 4]);
                al[mt][0] = __float_as_uint(pL[0]);
                al[mt][2] = __float_as_uint(pL[4]);
                al[mt][1] = __float_as_uint(pL[8 * GPITCH]);
                al[mt][3] = __float_as_uint(pL[8 * GPITCH + 4]);
            }
            unsigned bh[4][2], bl[4][2];
#pragma unroll
            for (int nt = 0; nt < 4; ++nt) {
                int n = wn * 32 + nt * 8 + g;
                const float* pH = BsHi + n * GPITCH + kk + tig;
                const float* pL = BsLo + n * GPITCH + kk + tig;
                bh[nt][0] = __float_as_uint(pH[0]);
                bh[nt][1] = __float_as_uint(pH[4]);
                bl[nt][0] = __float_as_uint(pL[0]);
                bl[nt][1] = __float_as_uint(pL[4]);
            }
#pragma unroll
            for (int mt = 0; mt < 4; ++mt) {
#pragma unroll
                for (int nt = 0; nt < 4; ++nt) {
                    mma_tf32(acc[mt][nt], ah[mt][0], ah[mt][1], ah[mt][2], ah[mt][3],
                             bh[nt][0], bh[nt][1]);
                    mma_tf32(acc[mt][nt], al[mt][0], al[mt][1], al[mt][2], al[mt][3],
                             bh[nt][0], bh[nt][1]);
                    mma_tf32(acc[mt][nt], ah[mt][0], ah[mt][1], ah[mt][2], ah[mt][3],
                             bl[nt][0], bl[nt][1]);
                }
            }
        }
        __syncthreads();
        if (kt + 1 < nKt) {
            store_tile(pfA, pfB);
        }
        __syncthreads();
    }

#pragma unroll
    for (int mt = 0; mt < 4; ++mt) {
#pragma unroll
        for (int nt = 0; nt < 4; ++nt) {
            int jj = bc * 128 + wn * 32 + nt * 8 + tig * 2;
#pragma unroll
            for (int half = 0; half < 2; ++half) {
                int ii = br * 128 + wm * 64 + mt * 16 + g + half * 8;
                float2 val;
                val.x = acc[mt][nt][half * 2 + 0];
                val.y = acc[mt][nt][half * 2 + 1];
                if (OUTMODE == 0) {
                    *(float2*)(C + (long)ii * N + jj) = val;
                } else {
                    int b = ii >> 9, l = ii & 511;
                    int h = jj >> 6, d = jj & 63;
                    *(float2*)(C + (((long)(b * 16 + h) * 512) + l) * 64 + d) = val;
                }
            }
        }
    }
}

// ====================================================================
// Tensor-core flash attention (tf32, 3-term compensation).
// BM=128 q rows per block, 8 warps (one m16 strip each), KV tiles of 64.
// Q fragments (hi/lo tf32) live in registers for the whole kernel.
// K/V stored hi/lo in smem; P round-trips through smem warp-locally.
// smem pitch 68 -> conflict-free fragment access (banks 4g+tig / 4tig+g).
// ====================================================================
#define APITCH 68
// smem float offsets
#define OFF_KHI 0
#define OFF_KLO (64*APITCH)
#define OFF_VHI (2*64*APITCH)
#define OFF_VLO (3*64*APITCH)
#define OFF_SS  (4*64*APITCH)            // 128*APITCH (also Q staging)
#define OFF_MS  (4*64*APITCH + 128*APITCH)
#define ATTN_SMEM_FLOATS (OFF_MS + 128*64/4)

__global__ void __launch_bounds__(256, 1) attn_tc(
    const float* __restrict__ Q,
    const float* __restrict__ Kb, long kBS, long kHS, int kRS,
    const float* __restrict__ Vb, long vBS, long vHS, int vRS,
    const unsigned int* __restrict__ mask,
    float* __restrict__ Ob, long oBS, long oHS, int oRS,
    int residual)
{
    extern __shared__ float sm[];
    float* Khi = sm + OFF_KHI;
    float* Klo = sm + OFF_KLO;
    float* Vhi = sm + OFF_VHI;
    float* Vlo = sm + OFF_VLO;
    float* Ss  = sm + OFF_SS;            // P matrix / Q staging
    unsigned char* Ms = (unsigned char*)(sm + OFF_MS);

    const int b  = blockIdx.z;
    const int h  = blockIdx.y;
    const int q0 = blockIdx.x * 128;

    const float* Qp = Q + (((long)(b*16 + h) * 512) + q0) * 64;
    const float* Kp = Kb + (long)b * kBS + (long)h * kHS;
    const float* Vp = Vb + (long)b * vBS + (long)h * vHS;
    const unsigned int* Mp = mask + (long)b * LL * LL + (long)q0 * LL;
    float* Op = Ob + (long)b * oBS + (long)h * oHS + (long)q0 * oRS;

    const int tid  = threadIdx.x;
    const int w    = tid >> 5;
    const int lane = tid & 31;
    const int g    = lane >> 2;    // 0..7
    const int tig  = lane & 3;     // 0..3
    const int r0   = w * 16 + g;   // block-local q row (also r0+8)

    // ---- stage Q into Ss, then pull fragments into registers ----
#pragma unroll
    for (int it = 0; it < 8; ++it) {
        int f = tid + it * 256;          // 0..2047 float4
        int row = f >> 4, c4 = f & 15;
        float4 v = *(const float4*)(Qp + (long)row * 64 + c4 * 4);
        float* dst = Ss + row * APITCH + c4 * 4;
        dst[0] = v.x; dst[1] = v.y; dst[2] = v.z; dst[3] = v.w;
    }
    __syncthreads();

    unsigned qhr[8][4], qlr[8][4];
#pragma unroll
    for (int kc = 0; kc < 8; ++kc) {
        float x0 = Ss[(r0)     * APITCH + kc * 8 + tig];
        float x1 = Ss[(r0 + 8) * APITCH + kc * 8 + tig];
        float x2 = Ss[(r0)     * APITCH + kc * 8 + tig + 4];
        float x3 = Ss[(r0 + 8) * APITCH + kc * 8 + tig + 4];
        split_tf32(x0, qhr[kc][0], qlr[kc][0]);
        split_tf32(x1, qhr[kc][1], qlr[kc][1]);
        split_tf32(x2, qhr[kc][2], qlr[kc][2]);
        split_tf32(x3, qhr[kc][3], qlr[kc][3]);
    }
    // Ss rows of warp w are only ever touched by warp w from here on.

    float oacc[8][4];
#pragma unroll
    for (int nt = 0; nt < 8; ++nt)
#pragma unroll
        for (int i = 0; i < 4; ++i) oacc[nt][i] = 0.f;

    float m0 = -1e30f, m1 = -1e30f, l0 = 0.f, l1 = 0.f;

    for (int kt = 0; kt < 8; ++kt) {
        const int k0 = kt * 64;

        // ---- load K, V (hi/lo split), mask tile ----
#pragma unroll
        for (int it = 0; it < 4; ++it) {
            int f = tid + it * 256;      // 0..1023
            int row = f >> 4, c4 = f & 15;
            float4 kv = *(const float4*)(Kp + (long)(k0 + row) * kRS + c4 * 4);
            float4 hi, lo;
            hi.x = __uint_as_float(f2tf32(kv.x)); lo.x = __uint_as_float(f2tf32(kv.x - hi.x));
            hi.y = __uint_as_float(f2tf32(kv.y)); lo.y = __uint_as_float(f2tf32(kv.y - hi.y));
            hi.z = __uint_as_float(f2tf32(kv.z)); lo.z = __uint_as_float(f2tf32(kv.z - hi.z));
            hi.w = __uint_as_float(f2tf32(kv.w)); lo.w = __uint_as_float(f2tf32(kv.w - hi.w));
            *(float4*)(Khi + row * APITCH + c4 * 4) = hi;
            *(float4*)(Klo + row * APITCH + c4 * 4) = lo;
            float4 vv = *(const float4*)(Vp + (long)(k0 + row) * vRS + c4 * 4);
            hi.x = __uint_as_float(f2tf32(vv.x)); lo.x = __uint_as_float(f2tf32(vv.x - hi.x));
            hi.y = __uint_as_float(f2tf32(vv.y)); lo.y = __uint_as_float(f2tf32(vv.y - hi.y));
            hi.z = __uint_as_float(f2tf32(vv.z)); lo.z = __uint_as_float(f2tf32(vv.z - hi.z));
            hi.w = __uint_as_float(f2tf32(vv.w)); lo.w = __uint_as_float(f2tf32(vv.w - hi.w));
            *(float4*)(Vhi + row * APITCH + c4 * 4) = hi;
            *(float4*)(Vlo + row * APITCH + c4 * 4) = lo;
        }
#pragma unroll
        for (int it = 0; it < 8; ++it) {
            int u = tid + it * 256;      // 0..2047
            int row = u >> 4, c4 = u & 15;
            uint4 m4 = *(const uint4*)(Mp + (long)row * LL + k0 + c4 * 4);
            uchar4 pk;
            pk.x = m4.x ? 1 : 0;
            pk.y = m4.y ? 1 : 0;
            pk.z = m4.z ? 1 : 0;
            pk.w = m4.w ? 1 : 0;
            ((uchar4*)Ms)[row * 16 + c4] = pk;
        }
        __syncthreads();

        // ---- S = Q K^T (3-term tf32) ----
        float sacc[8][4];
#pragma unroll
        for (int nt = 0; nt < 8; ++nt) {
#pragma unroll
            for (int i = 0; i < 4; ++i) sacc[nt][i] = 0.f;
#pragma unroll
            for (int kc = 0; kc < 8; ++kc) {
                const float* pH = Khi + (nt * 8 + g) * APITCH + kc * 8 + tig;
                const float* pL = Klo + (nt * 8 + g) * APITCH + kc * 8 + tig;
                unsigned bh0 = __float_as_uint(pH[0]);
                unsigned bh1 = __float_as_uint(pH[4]);
                unsigned bl0 = __float_as_uint(pL[0]);
                unsigned bl1 = __float_as_uint(pL[4]);
                mma_tf32(sacc[nt], qhr[kc][0], qhr[kc][1], qhr[kc][2], qhr[kc][3], bh0, bh1);
                mma_tf32(sacc[nt], qlr[kc][0], qlr[kc][1], qlr[kc][2], qlr[kc][3], bh0, bh1);
                mma_tf32(sacc[nt], qhr[kc][0], qhr[kc][1], qhr[kc][2], qhr[kc][3], bl0, bl1);
            }
        }

        // ---- scale + mask ----
#pragma unroll
        for (int nt = 0; nt < 8; ++nt) {
            uchar2 mA = *(const uchar2*)(Ms + (r0)     * 64 + nt * 8 + tig * 2);
            uchar2 mB = *(const uchar2*)(Ms + (r0 + 8) * 64 + nt * 8 + tig * 2);
            sacc[nt][0] = mA.x ? -1e9f : sacc[nt][0] * 0.125f;
            sacc[nt][1] = mA.y ? -1e9f : sacc[nt][1] * 0.125f;
            sacc[nt][2] = mB.x ? -1e9f : sacc[nt][2] * 0.125f;
            sacc[nt][3] = mB.y ? -1e9f : sacc[nt][3] * 0.125f;
        }

        // ---- online softmax (warp-local, quad reductions) ----
        float mx0 = -3.0e38f, mx1 = -3.0e38f;
#pragma unroll
        for (int nt = 0; nt < 8; ++nt) {
            mx0 = fmaxf(mx0, fmaxf(sacc[nt][0], sacc[nt][1]));
            mx1 = fmaxf(mx1, fmaxf(sacc[nt][2], sacc[nt][3]));
        }
        mx0 = fmaxf(mx0, __shfl_xor_sync(0xffffffffu, mx0, 1));
        mx0 = fmaxf(mx0, __shfl_xor_sync(0xffffffffu, mx0, 2));
        mx1 = fmaxf(mx1, __shfl_xor_sync(0xffffffffu, mx1, 1));
        mx1 = fmaxf(mx1, __shfl_xor_sync(0xffffffffu, mx1, 2));

        float mn0 = fmaxf(m0, mx0), mn1 = fmaxf(m1, mx1);
        float al0 = __expf(m0 - mn0), al1 = __expf(m1 - mn1);
        m0 = mn0; m1 = mn1;

        float sum0 = 0.f, sum1 = 0.f;
#pragma unroll
        for (int nt = 0; nt < 8; ++nt) {
            float p00 = __expf(sacc[nt][0] - m0);
            float p01 = __expf(sacc[nt][1] - m0);
            float p10 = __expf(sacc[nt][2] - m1);
            float p11 = __expf(sacc[nt][3] - m1);
            sum0 += p00 + p01;
            sum1 += p10 + p11;
            *(float2*)(Ss + (r0)     * APITCH + nt * 8 + tig * 2) = make_float2(p00, p01);
            *(float2*)(Ss + (r0 + 8) * APITCH + nt * 8 + tig * 2) = make_float2(p10, p11);
        }
        sum0 += __shfl_xor_sync(0xffffffffu, sum0, 1);
        sum0 += __shfl_xor_sync(0xffffffffu, sum0, 2);
        sum1 += __shfl_xor_sync(0xffffffffu, sum1, 1);
        sum1 += __shfl_xor_sync(0xffffffffu, sum1, 2);
        l0 = l0 * al0 + sum0;
        l1 = l1 * al1 + sum1;

#pragma unroll
        for (int nt = 0; nt < 8; ++nt) {
            oacc[nt][0] *= al0; oacc[nt][1] *= al0;
            oacc[nt][2] *= al1; oacc[nt][3] *= al1;
        }
        __syncwarp();

        // ---- O += P V (3-term tf32) ----
#pragma unroll
        for (int kc = 0; kc < 8; ++kc) {
            float p0 = Ss[(r0)     * APITCH + kc * 8 + tig];
            float p1 = Ss[(r0 + 8) * APITCH + kc * 8 + tig];
            float p2 = Ss[(r0)     * APITCH + kc * 8 + tig + 4];
            float p3 = Ss[(r0 + 8) * APITCH + kc * 8 + tig + 4];
            unsigned ph[4], pl[4];
            split_tf32(p0, ph[0], pl[0]);
            split_tf32(p1, ph[1], pl[1]);
            split_tf32(p2, ph[2], pl[2]);
            split_tf32(p3, ph[3], pl[3]);
            const float* vH0 = Vhi + (kc * 8 + tig)     * APITCH + g;
            const float* vH1 = Vhi + (kc * 8 + tig + 4) * APITCH + g;
            const float* vL0 = Vlo + (kc * 8 + tig)     * APITCH + g;
            const float* vL1 = Vlo + (kc * 8 + tig + 4) * APITCH + g;
#pragma unroll
            for (int nt = 0; nt < 8; ++nt) {
                unsigned bh0 = __float_as_uint(vH0[nt * 8]);
                unsigned bh1 = __float_as_uint(vH1[nt * 8]);
                unsigned bl0 = __float_as_uint(vL0[nt * 8]);
                unsigned bl1 = __float_as_uint(vL1[nt * 8]);
                mma_tf32(oacc[nt], ph[0], ph[1], ph[2], ph[3], bh0, bh1);
                mma_tf32(oacc[nt], pl[0], pl[1], pl[2], pl[3], bh0, bh1);
                mma_tf32(oacc[nt], ph[0], ph[1], ph[2], ph[3], bl0, bl1);
            }
        }
        __syncthreads();
    }

    // ---- finalize: /l, residual, store ----
    float inv0 = 1.0f / l0, inv1 = 1.0f / l1;
#pragma unroll
    for (int nt = 0; nt < 8; ++nt) {
        int c = nt * 8 + tig * 2;
        float2 v0 = make_float2(oacc[nt][0] * inv0, oacc[nt][1] * inv0);
        float2 v1 = make_float2(oacc[nt][2] * inv1, oacc[nt][3] * inv1);
        if (residual) {
            float2 qres0 = *(const float2*)(Qp + (long)(r0)     * 64 + c);
            float2 qres1 = *(const float2*)(Qp + (long)(r0 + 8) * 64 + c);
            v0.x += qres0.x; v0.y += qres0.y;
            v1.x += qres1.x; v1.y += qres1.y;
        }
        *(float2*)(Op + (long)(r0)     * oRS + c) = v0;
        *(float2*)(Op + (long)(r0 + 8) * oRS + c) = v1;
    }
}

// ====================================================================
extern "C" void kernel_launch(void* const* d_in, const int* in_sizes, int n_in,
                              void* d_out, int out_size)
{
    (void)in_sizes; (void)n_in; (void)out_size;
    const float* v   = (const float*)d_in[0];
    const float* k   = (const float*)d_in[1];
    const float* q   = (const float*)d_in[2];
    const float* img = (const float*)d_in[3];
    const float* Wv  = (const float*)d_in[4];
    const float* Wk  = (const float*)d_in[5];
    const float* Wq  = (const float*)d_in[6];
    const float* Wm  = (const float*)d_in[7];
    const unsigned int* absm = (const unsigned int*)d_in[8];
    const unsigned int* mask = (const unsigned int*)d_in[9];
    float* out = (float*)d_out;

    float *vh, *kh, *qh, *qn, *att;
    cudaGetSymbolAddress((void**)&vh,  g_vh);
    cudaGetSymbolAddress((void**)&kh,  g_kh);
    cudaGetSymbolAddress((void**)&qh,  g_qh);
    cudaGetSymbolAddress((void**)&qn,  g_qn);
    cudaGetSymbolAddress((void**)&att, g_att);

    const int gsmem = 4 * 128 * GPITCH * sizeof(float);   // 73728
    cudaFuncSetAttribute(gemm_tf32<0>,
                         cudaFuncAttributeMaxDynamicSharedMemorySize, gsmem);
    cudaFuncSetAttribute(gemm_tf32<1>,
                         cudaFuncAttributeMaxDynamicSharedMemorySize, gsmem);

    dim3 gg(HS / 128, MROWS / 128);   // (8, 64)
    gemm_tf32<1><<<gg, 256, gsmem>>>(v, Wv, vh, MROWS, HS, HS);
    gemm_tf32<1><<<gg, 256, gsmem>>>(k, Wk, kh, MROWS, HS, HS);
    gemm_tf32<1><<<gg, 256, gsmem>>>(q, Wq, qh, MROWS, HS, HS);

    const int asmem = ATTN_SMEM_FLOATS * sizeof(float);   // ~112.6 KB
    cudaFuncSetAttribute(attn_tc,
                         cudaFuncAttributeMaxDynamicSharedMemorySize, asmem);

    dim3 ga(LL / 128, HH, BB);   // (4, 16, 16)
    // Stage 1: modulate — K=V=img_abs (strided heads), residual, out -> g_qn [B,H,L,D]
    attn_tc<<<ga, 256, asmem>>>(
        qh,
        img, (long)LL * HS, 64L, HS,
        img, (long)LL * HS, 64L, HS,
        absm,
        qn,  (long)HH * LL * DD, (long)LL * DD, DD,
        1);
    // Stage 2: main attention — K=kh, V=vh, out -> g_att [B,L,H*D]
    attn_tc<<<ga, 256, asmem>>>(
        qn,
        kh, (long)HH * LL * DD, (long)LL * DD, DD,
        vh, (long)HH * LL * DD, (long)LL * DD, DD,
        mask,
        att, (long)LL * HS, 64L, HS,
        0);

    gemm_tf32<0><<<gg, 256, gsmem>>>(att, Wm, out, MROWS, HS, HS);
}

// round 5
// speedup vs baseline: 2.3298x; 1.4191x over previous
#include <cuda_runtime.h>
#include <cuda_bf16.h>

// Problem constants
#define BB 16
#define LL 512
#define HS 1024
#define HH 16
#define DD 64
#define MROWS (BB*LL)        // 8192

// -------------------- scratch (allocation-free) --------------------
__device__ float g_vh[BB*HH*LL*DD];   // [B,H,L,D]
__device__ float g_kh[BB*HH*LL*DD];
__device__ float g_qh[BB*HH*LL*DD];
__device__ float g_qn[BB*HH*LL*DD];   // modulated q
__device__ float g_att[BB*LL*HS];     // [B,L,H*D]

// ------------------ tf32 helpers (kept for attention PV) ------------------
__device__ __forceinline__ unsigned f2tf32(float x) {
    unsigned r;
    asm("cvt.rna.tf32.f32 %0, %1;" : "=r"(r) : "f"(x));
    return r;
}

__device__ __forceinline__ void split_tf32(float x, unsigned &hi, unsigned &lo) {
    hi = f2tf32(x);
    lo = f2tf32(x - __uint_as_float(hi));
}

__device__ __forceinline__ void mma_tf32(float d[4],
                                         unsigned a0, unsigned a1, unsigned a2, unsigned a3,
                                         unsigned b0, unsigned b1)
{
    asm volatile(
        "mma.sync.aligned.m16n8k8.row.col.f32.tf32.tf32.f32 "
        "{%0,%1,%2,%3}, {%4,%5,%6,%7}, {%8,%9}, {%0,%1,%2,%3};\n"
        : "+f"(d[0]), "+f"(d[1]), "+f"(d[2]), "+f"(d[3])
        : "r"(a0), "r"(a1), "r"(a2), "r"(a3), "r"(b0), "r"(b1));
}

// ------------------ bf16 helpers ------------------
__device__ __forceinline__ unsigned pack2bf(__nv_bfloat16 a, __nv_bfloat16 b) {
    __nv_bfloat162 t; t.x = a; t.y = b;
    return reinterpret_cast<unsigned&>(t);
}

// split two floats into packed bf16 hi pair + bf16 lo pair (k-adjacent)
__device__ __forceinline__ void bsplit2(float x0, float x1, unsigned &hi, unsigned &lo) {
    __nv_bfloat16 h0 = __float2bfloat16(x0);
    __nv_bfloat16 h1 = __float2bfloat16(x1);
    __nv_bfloat16 l0 = __float2bfloat16(x0 - __bfloat162float(h0));
    __nv_bfloat16 l1 = __float2bfloat16(x1 - __bfloat162float(h1));
    hi = pack2bf(h0, h1);
    lo = pack2bf(l0, l1);
}

__device__ __forceinline__ void mma_bf16(float d[4],
                                         unsigned a0, unsigned a1, unsigned a2, unsigned a3,
                                         unsigned b0, unsigned b1)
{
    asm volatile(
        "mma.sync.aligned.m16n8k16.row.col.f32.bf16.bf16.f32 "
        "{%0,%1,%2,%3}, {%4,%5,%6,%7}, {%8,%9}, {%0,%1,%2,%3};\n"
        : "+f"(d[0]), "+f"(d[1]), "+f"(d[2]), "+f"(d[3])
        : "r"(a0), "r"(a1), "r"(a2), "r"(a3), "r"(b0), "r"(b1));
}

// ====================================================================
// bf16 tensor-core GEMM with 3-term compensation (hi*hi + lo*hi + hi*lo):
//   C[M,N] = A[M,K] @ Bw[N,K]^T   (both K-contiguous, fp32 in/out)
// Block tile 128x128, BK=32, 256 threads (8 warps 2x4), warp tile 64x32.
// mma.m16n8k16.bf16; C-fragment layout identical to m16n8k8 -> same epilogue.
// smem: bf16 hi/lo copies of A and B tiles, pitch 40 bf16 (80B = 20 banks,
// bank(frag) = 20g + tig, all-distinct within quad pattern).
// ====================================================================
#define BP 40   // bf16 pitch

template<int OUTMODE>
__global__ void __launch_bounds__(256, 1) gemm_bf16(const float* __restrict__ A,
                                                    const float* __restrict__ Bw,
                                                    float* __restrict__ C,
                                                    int M, int N, int K)
{
    extern __shared__ float smf[];
    __nv_bfloat16* AsHi = (__nv_bfloat16*)smf;       // 128*BP each
    __nv_bfloat16* AsLo = AsHi + 128 * BP;
    __nv_bfloat16* BsHi = AsLo + 128 * BP;
    __nv_bfloat16* BsLo = BsHi + 128 * BP;

    const int tid  = threadIdx.x;
    const int br   = blockIdx.y;
    const int bc   = blockIdx.x;
    const int wid  = tid >> 5;
    const int lane = tid & 31;
    const int g    = lane >> 2;
    const int tig  = lane & 3;

    const int wm = wid >> 2;
    const int wn = wid & 3;

    const float* Ab = A  + (long)br * 128 * K;
    const float* Bb = Bw + (long)bc * 128 * K;

    float acc[4][4][4];
#pragma unroll
    for (int mt = 0; mt < 4; ++mt)
#pragma unroll
        for (int nt = 0; nt < 4; ++nt)
#pragma unroll
            for (int r = 0; r < 4; ++r) acc[mt][nt][r] = 0.f;

    const int ldrow = tid >> 3;          // 0..31 (advance by 32)
    const int ldkq  = tid & 7;           // float4 slot (k = ldkq*4..+3)

    auto store_tile = [&](const float4* av, const float4* bv) {
#pragma unroll
        for (int it = 0; it < 4; ++it) {
            int row = ldrow + it * 32;
            float4 a = av[it];
            unsigned h01, l01, h23, l23;
            bsplit2(a.x, a.y, h01, l01);
            bsplit2(a.z, a.w, h23, l23);
            *(uint2*)(AsHi + row * BP + ldkq * 4) = make_uint2(h01, h23);
            *(uint2*)(AsLo + row * BP + ldkq * 4) = make_uint2(l01, l23);
            float4 b = bv[it];
            bsplit2(b.x, b.y, h01, l01);
            bsplit2(b.z, b.w, h23, l23);
            *(uint2*)(BsHi + row * BP + ldkq * 4) = make_uint2(h01, h23);
            *(uint2*)(BsLo + row * BP + ldkq * 4) = make_uint2(l01, l23);
        }
    };

    float4 pfA[4], pfB[4];
#pragma unroll
    for (int it = 0; it < 4; ++it) {
        int row = ldrow + it * 32;
        pfA[it] = *(const float4*)(Ab + (long)row * K + ldkq * 4);
        pfB[it] = *(const float4*)(Bb + (long)row * K + ldkq * 4);
    }
    store_tile(pfA, pfB);
    __syncthreads();

    const int nKt = K / 32;
    for (int kt = 0; kt < nKt; ++kt) {
        if (kt + 1 < nKt) {
            int k0 = (kt + 1) * 32;
#pragma unroll
            for (int it = 0; it < 4; ++it) {
                int row = ldrow + it * 32;
                pfA[it] = *(const float4*)(Ab + (long)row * K + k0 + ldkq * 4);
                pfB[it] = *(const float4*)(Bb + (long)row * K + k0 + ldkq * 4);
            }
        }

        // 2 k-steps of 16
#pragma unroll
        for (int ks = 0; ks < 2; ++ks) {
            const int kk = ks * 16;
            unsigned ah[4][4], al[4][4];
#pragma unroll
            for (int mt = 0; mt < 4; ++mt) {
                int m = wm * 64 + mt * 16 + g;
                const __nv_bfloat16* pH = AsHi + m * BP + kk + tig * 2;
                const __nv_bfloat16* pL = AsLo + m * BP + kk + tig * 2;
                ah[mt][0] = *(const unsigned*)(pH);
                ah[mt][1] = *(const unsigned*)(pH + 8 * BP);
                ah[mt][2] = *(const unsigned*)(pH + 8);
                ah[mt][3] = *(const unsigned*)(pH + 8 * BP + 8);
                al[mt][0] = *(const unsigned*)(pL);
                al[mt][1] = *(const unsigned*)(pL + 8 * BP);
                al[mt][2] = *(const unsigned*)(pL + 8);
                al[mt][3] = *(const unsigned*)(pL + 8 * BP + 8);
            }
            unsigned bh[4][2], bl[4][2];
#pragma unroll
            for (int nt = 0; nt < 4; ++nt) {
                int n = wn * 32 + nt * 8 + g;
                const __nv_bfloat16* pH = BsHi + n * BP + kk + tig * 2;
                const __nv_bfloat16* pL = BsLo + n * BP + kk + tig * 2;
                bh[nt][0] = *(const unsigned*)(pH);
                bh[nt][1] = *(const unsigned*)(pH + 8);
                bl[nt][0] = *(const unsigned*)(pL);
                bl[nt][1] = *(const unsigned*)(pL + 8);
            }
#pragma unroll
            for (int mt = 0; mt < 4; ++mt) {
#pragma unroll
                for (int nt = 0; nt < 4; ++nt) {
                    mma_bf16(acc[mt][nt], ah[mt][0], ah[mt][1], ah[mt][2], ah[mt][3],
                             bh[nt][0], bh[nt][1]);
                    mma_bf16(acc[mt][nt], al[mt][0], al[mt][1], al[mt][2], al[mt][3],
                             bh[nt][0], bh[nt][1]);
                    mma_bf16(acc[mt][nt], ah[mt][0], ah[mt][1], ah[mt][2], ah[mt][3],
                             bl[nt][0], bl[nt][1]);
                }
            }
        }
        __syncthreads();
        if (kt + 1 < nKt) {
            store_tile(pfA, pfB);
        }
        __syncthreads();
    }

#pragma unroll
    for (int mt = 0; mt < 4; ++mt) {
#pragma unroll
        for (int nt = 0; nt < 4; ++nt) {
            int jj = bc * 128 + wn * 32 + nt * 8 + tig * 2;
#pragma unroll
            for (int half = 0; half < 2; ++half) {
                int ii = br * 128 + wm * 64 + mt * 16 + g + half * 8;
                float2 val;
                val.x = acc[mt][nt][half * 2 + 0];
                val.y = acc[mt][nt][half * 2 + 1];
                if (OUTMODE == 0) {
                    *(float2*)(C + (long)ii * N + jj) = val;
                } else {
                    int b = ii >> 9, l = ii & 511;
                    int h = jj >> 6, d = jj & 63;
                    *(float2*)(C + (((long)(b * 16 + h) * 512) + l) * 64 + d) = val;
                }
            }
        }
    }
}

// ====================================================================
// Tensor-core flash attention.
// S = QK^T: bf16 m16n8k16 3-term (K tile is d-contiguous -> packed frags).
// PV: tf32 m16n8k8 3-term (V k-dim non-contiguous; unchanged from R4).
// BM=128 q rows, 8 warps (m16 strip each), KV tiles of 64. Softmax warp-local.
// ====================================================================
#define AP 68          // fp32 pitch (V, Ss)
#define KP 72          // bf16 pitch for K tiles (144B = 36 banks -> bank 4g+tig)
// smem float offsets
#define OFF_VHI 0
#define OFF_VLO (64*AP)                 // 4352
#define OFF_SS  (2*64*AP)               // 8704
#define OFF_KHI (2*64*AP + 128*AP)      // 17408 (floats; bf16 array)
#define OFF_KLO (OFF_KHI + (64*KP)/2)   // 19712
#define OFF_MS  (OFF_KLO + (64*KP)/2)   // 22016
#define ATTN_SMEM_FLOATS (OFF_MS + 128*64/4)   // 24064 floats = 96256 B

__global__ void __launch_bounds__(256, 1) attn_tc(
    const float* __restrict__ Q,
    const float* __restrict__ Kb, long kBS, long kHS, int kRS,
    const float* __restrict__ Vb, long vBS, long vHS, int vRS,
    const unsigned int* __restrict__ mask,
    float* __restrict__ Ob, long oBS, long oHS, int oRS,
    int residual)
{
    extern __shared__ float sm[];
    float* Vhi = sm + OFF_VHI;
    float* Vlo = sm + OFF_VLO;
    float* Ss  = sm + OFF_SS;            // P matrix / Q staging (fp32, pitch AP)
    __nv_bfloat16* Khi = (__nv_bfloat16*)(sm + OFF_KHI);
    __nv_bfloat16* Klo = (__nv_bfloat16*)(sm + OFF_KLO);
    unsigned char* Ms = (unsigned char*)(sm + OFF_MS);

    const int b  = blockIdx.z;
    const int h  = blockIdx.y;
    const int q0 = blockIdx.x * 128;

    const float* Qp = Q + (((long)(b*16 + h) * 512) + q0) * 64;
    const float* Kp = Kb + (long)b * kBS + (long)h * kHS;
    const float* Vp = Vb + (long)b * vBS + (long)h * vHS;
    const unsigned int* Mp = mask + (long)b * LL * LL + (long)q0 * LL;
    float* Op = Ob + (long)b * oBS + (long)h * oHS + (long)q0 * oRS;

    const int tid  = threadIdx.x;
    const int w    = tid >> 5;
    const int lane = tid & 31;
    const int g    = lane >> 2;    // 0..7
    const int tig  = lane & 3;     // 0..3
    const int r0   = w * 16 + g;   // block-local q row (also r0+8)

    // ---- stage Q into Ss, then pull bf16 hi/lo fragments into registers ----
#pragma unroll
    for (int it = 0; it < 8; ++it) {
        int f = tid + it * 256;          // 0..2047 float4
        int row = f >> 4, c4 = f & 15;
        float4 v = *(const float4*)(Qp + (long)row * 64 + c4 * 4);
        float* dst = Ss + row * AP + c4 * 4;
        dst[0] = v.x; dst[1] = v.y; dst[2] = v.z; dst[3] = v.w;
    }
    __syncthreads();

    unsigned qh[4][4], ql[4][4];   // 4 k16-chunks, 4 packed regs each
#pragma unroll
    for (int kc = 0; kc < 4; ++kc) {
        const float* p0 = Ss + (r0)     * AP + kc * 16 + tig * 2;
        const float* p1 = Ss + (r0 + 8) * AP + kc * 16 + tig * 2;
        bsplit2(p0[0], p0[1], qh[kc][0], ql[kc][0]);
        bsplit2(p1[0], p1[1], qh[kc][1], ql[kc][1]);
        bsplit2(p0[8], p0[9], qh[kc][2], ql[kc][2]);
        bsplit2(p1[8], p1[9], qh[kc][3], ql[kc][3]);
    }
    // Ss rows of warp w are only touched by warp w from here on.

    float oacc[8][4];
#pragma unroll
    for (int nt = 0; nt < 8; ++nt)
#pragma unroll
        for (int i = 0; i < 4; ++i) oacc[nt][i] = 0.f;

    float m0 = -1e30f, m1 = -1e30f, l0 = 0.f, l1 = 0.f;

    for (int kt = 0; kt < 8; ++kt) {
        const int k0 = kt * 64;

        // ---- load K (bf16 hi/lo), V (tf32 hi/lo), mask ----
#pragma unroll
        for (int it = 0; it < 4; ++it) {
            int f = tid + it * 256;      // 0..1023
            int row = f >> 4, c4 = f & 15;
            float4 kv = *(const float4*)(Kp + (long)(k0 + row) * kRS + c4 * 4);
            unsigned h01, l01, h23, l23;
            bsplit2(kv.x, kv.y, h01, l01);
            bsplit2(kv.z, kv.w, h23, l23);
            *(uint2*)(Khi + row * KP + c4 * 4) = make_uint2(h01, h23);
            *(uint2*)(Klo + row * KP + c4 * 4) = make_uint2(l01, l23);
            float4 vv = *(const float4*)(Vp + (long)(k0 + row) * vRS + c4 * 4);
            float4 hi, lo;
            hi.x = __uint_as_float(f2tf32(vv.x)); lo.x = __uint_as_float(f2tf32(vv.x - hi.x));
            hi.y = __uint_as_float(f2tf32(vv.y)); lo.y = __uint_as_float(f2tf32(vv.y - hi.y));
            hi.z = __uint_as_float(f2tf32(vv.z)); lo.z = __uint_as_float(f2tf32(vv.z - hi.z));
            hi.w = __uint_as_float(f2tf32(vv.w)); lo.w = __uint_as_float(f2tf32(vv.w - hi.w));
            *(float4*)(Vhi + row * AP + c4 * 4) = hi;
            *(float4*)(Vlo + row * AP + c4 * 4) = lo;
        }
#pragma unroll
        for (int it = 0; it < 8; ++it) {
            int u = tid + it * 256;      // 0..2047
            int row = u >> 4, c4 = u & 15;
            uint4 m4 = *(const uint4*)(Mp + (long)row * LL + k0 + c4 * 4);
            uchar4 pk;
            pk.x = m4.x ? 1 : 0;
            pk.y = m4.y ? 1 : 0;
            pk.z = m4.z ? 1 : 0;
            pk.w = m4.w ? 1 : 0;
            ((uchar4*)Ms)[row * 16 + c4] = pk;
        }
        __syncthreads();

        // ---- S = Q K^T (3-term bf16, k16) ----
        float sacc[8][4];
#pragma unroll
        for (int nt = 0; nt < 8; ++nt) {
#pragma unroll
            for (int i = 0; i < 4; ++i) sacc[nt][i] = 0.f;
#pragma unroll
            for (int kc = 0; kc < 4; ++kc) {
                const __nv_bfloat16* pH = Khi + (nt * 8 + g) * KP + kc * 16 + tig * 2;
                const __nv_bfloat16* pL = Klo + (nt * 8 + g) * KP + kc * 16 + tig * 2;
                unsigned bh0 = *(const unsigned*)(pH);
                unsigned bh1 = *(const unsigned*)(pH + 8);
                unsigned bl0 = *(const unsigned*)(pL);
                unsigned bl1 = *(const unsigned*)(pL + 8);
                mma_bf16(sacc[nt], qh[kc][0], qh[kc][1], qh[kc][2], qh[kc][3], bh0, bh1);
                mma_bf16(sacc[nt], ql[kc][0], ql[kc][1], ql[kc][2], ql[kc][3], bh0, bh1);
                mma_bf16(sacc[nt], qh[kc][0], qh[kc][1], qh[kc][2], qh[kc][3], bl0, bl1);
            }
        }

        // ---- scale + mask ----
#pragma unroll
        for (int nt = 0; nt < 8; ++nt) {
            uchar2 mA = *(const uchar2*)(Ms + (r0)     * 64 + nt * 8 + tig * 2);
            uchar2 mB = *(const uchar2*)(Ms + (r0 + 8) * 64 + nt * 8 + tig * 2);
            sacc[nt][0] = mA.x ? -1e9f : sacc[nt][0] * 0.125f;
            sacc[nt][1] = mA.y ? -1e9f : sacc[nt][1] * 0.125f;
            sacc[nt][2] = mB.x ? -1e9f : sacc[nt][2] * 0.125f;
            sacc[nt][3] = mB.y ? -1e9f : sacc[nt][3] * 0.125f;
        }

        // ---- online softmax (warp-local, quad reductions) ----
        float mx0 = -3.0e38f, mx1 = -3.0e38f;
#pragma unroll
        for (int nt = 0; nt < 8; ++nt) {
            mx0 = fmaxf(mx0, fmaxf(sacc[nt][0], sacc[nt][1]));
            mx1 = fmaxf(mx1, fmaxf(sacc[nt][2], sacc[nt][3]));
        }
        mx0 = fmaxf(mx0, __shfl_xor_sync(0xffffffffu, mx0, 1));
        mx0 = fmaxf(mx0, __shfl_xor_sync(0xffffffffu, mx0, 2));
        mx1 = fmaxf(mx1, __shfl_xor_sync(0xffffffffu, mx1, 1));
        mx1 = fmaxf(mx1, __shfl_xor_sync(0xffffffffu, mx1, 2));

        float mn0 = fmaxf(m0, mx0), mn1 = fmaxf(m1, mx1);
        float al0 = __expf(m0 - mn0), al1 = __expf(m1 - mn1);
        m0 = mn0; m1 = mn1;

        float sum0 = 0.f, sum1 = 0.f;
#pragma unroll
        for (int nt = 0; nt < 8; ++nt) {
            float p00 = __expf(sacc[nt][0] - m0);
            float p01 = __expf(sacc[nt][1] - m0);
            float p10 = __expf(sacc[nt][2] - m1);
            float p11 = __expf(sacc[nt][3] - m1);
            sum0 += p00 + p01;
            sum1 += p10 + p11;
            *(float2*)(Ss + (r0)     * AP + nt * 8 + tig * 2) = make_float2(p00, p01);
            *(float2*)(Ss + (r0 + 8) * AP + nt * 8 + tig * 2) = make_float2(p10, p11);
        }
        sum0 += __shfl_xor_sync(0xffffffffu, sum0, 1);
        sum0 += __shfl_xor_sync(0xffffffffu, sum0, 2);
        sum1 += __shfl_xor_sync(0xffffffffu, sum1, 1);
        sum1 += __shfl_xor_sync(0xffffffffu, sum1, 2);
        l0 = l0 * al0 + sum0;
        l1 = l1 * al1 + sum1;

#pragma unroll
        for (int nt = 0; nt < 8; ++nt) {
            oacc[nt][0] *= al0; oacc[nt][1] *= al0;
            oacc[nt][2] *= al1; oacc[nt][3] *= al1;
        }
        __syncwarp();

        // ---- O += P V (3-term tf32, k8) ----
#pragma unroll
        for (int kc = 0; kc < 8; ++kc) {
            float p0 = Ss[(r0)     * AP + kc * 8 + tig];
            float p1 = Ss[(r0 + 8) * AP + kc * 8 + tig];
            float p2 = Ss[(r0)     * AP + kc * 8 + tig + 4];
            float p3 = Ss[(r0 + 8) * AP + kc * 8 + tig + 4];
            unsigned ph[4], pl[4];
            split_tf32(p0, ph[0], pl[0]);
            split_tf32(p1, ph[1], pl[1]);
            split_tf32(p2, ph[2], pl[2]);
            split_tf32(p3, ph[3], pl[3]);
            const float* vH0 = Vhi + (kc * 8 + tig)     * AP + g;
            const float* vH1 = Vhi + (kc * 8 + tig + 4) * AP + g;
            const float* vL0 = Vlo + (kc * 8 + tig)     * AP + g;
            const float* vL1 = Vlo + (kc * 8 + tig + 4) * AP + g;
#pragma unroll
            for (int nt = 0; nt < 8; ++nt) {
                unsigned bh0 = __float_as_uint(vH0[nt * 8]);
                unsigned bh1 = __float_as_uint(vH1[nt * 8]);
                unsigned bl0 = __float_as_uint(vL0[nt * 8]);
                unsigned bl1 = __float_as_uint(vL1[nt * 8]);
                mma_tf32(oacc[nt], ph[0], ph[1], ph[2], ph[3], bh0, bh1);
                mma_tf32(oacc[nt], pl[0], pl[1], pl[2], pl[3], bh0, bh1);
                mma_tf32(oacc[nt], ph[0], ph[1], ph[2], ph[3], bl0, bl1);
            }
        }
        __syncthreads();
    }

    // ---- finalize: /l, residual, store ----
    float inv0 = 1.0f / l0, inv1 = 1.0f / l1;
#pragma unroll
    for (int nt = 0; nt < 8; ++nt) {
        int c = nt * 8 + tig * 2;
        float2 v0 = make_float2(oacc[nt][0] * inv0, oacc[nt][1] * inv0);
        float2 v1 = make_float2(oacc[nt][2] * inv1, oacc[nt][3] * inv1);
        if (residual) {
            float2 qres0 = *(const float2*)(Qp + (long)(r0)     * 64 + c);
            float2 qres1 = *(const float2*)(Qp + (long)(r0 + 8) * 64 + c);
            v0.x += qres0.x; v0.y += qres0.y;
            v1.x += qres1.x; v1.y += qres1.y;
        }
        *(float2*)(Op + (long)(r0)     * oRS + c) = v0;
        *(float2*)(Op + (long)(r0 + 8) * oRS + c) = v1;
    }
}

// ====================================================================
extern "C" void kernel_launch(void* const* d_in, const int* in_sizes, int n_in,
                              void* d_out, int out_size)
{
    (void)in_sizes; (void)n_in; (void)out_size;
    const float* v   = (const float*)d_in[0];
    const float* k   = (const float*)d_in[1];
    const float* q   = (const float*)d_in[2];
    const float* img = (const float*)d_in[3];
    const float* Wv  = (const float*)d_in[4];
    const float* Wk  = (const float*)d_in[5];
    const float* Wq  = (const float*)d_in[6];
    const float* Wm  = (const float*)d_in[7];
    const unsigned int* absm = (const unsigned int*)d_in[8];
    const unsigned int* mask = (const unsigned int*)d_in[9];
    float* out = (float*)d_out;

    float *vh, *kh, *qh, *qn, *att;
    cudaGetSymbolAddress((void**)&vh,  g_vh);
    cudaGetSymbolAddress((void**)&kh,  g_kh);
    cudaGetSymbolAddress((void**)&qh,  g_qh);
    cudaGetSymbolAddress((void**)&qn,  g_qn);
    cudaGetSymbolAddress((void**)&att, g_att);

    const int gsmem = 4 * 128 * BP * (int)sizeof(__nv_bfloat16);   // 40960
    cudaFuncSetAttribute(gemm_bf16<0>,
                         cudaFuncAttributeMaxDynamicSharedMemorySize, gsmem);
    cudaFuncSetAttribute(gemm_bf16<1>,
                         cudaFuncAttributeMaxDynamicSharedMemorySize, gsmem);

    dim3 gg(HS / 128, MROWS / 128);   // (8, 64)
    gemm_bf16<1><<<gg, 256, gsmem>>>(v, Wv, vh, MROWS, HS, HS);
    gemm_bf16<1><<<gg, 256, gsmem>>>(k, Wk, kh, MROWS, HS, HS);
    gemm_bf16<1><<<gg, 256, gsmem>>>(q, Wq, qh, MROWS, HS, HS);

    const int asmem = ATTN_SMEM_FLOATS * (int)sizeof(float);   // 96256
    cudaFuncSetAttribute(attn_tc,
                         cudaFuncAttributeMaxDynamicSharedMemorySize, asmem);

    dim3 ga(LL / 128, HH, BB);   // (4, 16, 16)
    // Stage 1: modulate — K=V=img_abs (strided heads), residual, out -> g_qn [B,H,L,D]
    attn_tc<<<ga, 256, asmem>>>(
        qh,
        img, (long)LL * HS, 64L, HS,
        img, (long)LL * HS, 64L, HS,
        absm,
        qn,  (long)HH * LL * DD, (long)LL * DD, DD,
        1);
    // Stage 2: main attention — K=kh, V=vh, out -> g_att [B,L,H*D]
    attn_tc<<<ga, 256, asmem>>>(
        qn,
        kh, (long)HH * LL * DD, (long)LL * DD, DD,
        vh, (long)HH * LL * DD, (long)LL * DD, DD,
        mask,
        att, (long)LL * HS, 64L, HS,
        0);

    gemm_bf16<0><<<gg, 256, gsmem>>>(att, Wm, out, MROWS, HS, HS);
}

// round 6
// speedup vs baseline: 2.5596x; 1.0986x over previous
#include <cuda_runtime.h>
#include <cuda_bf16.h>

// Problem constants
#define BB 16
#define LL 512
#define HS 1024
#define HH 16
#define DD 64
#define MROWS (BB*LL)        // 8192

// -------------------- scratch (allocation-free) --------------------
__device__ float g_vh[BB*HH*LL*DD];   // [B,H,L,D]
__device__ float g_kh[BB*HH*LL*DD];
__device__ float g_qh[BB*HH*LL*DD];
__device__ float g_qn[BB*HH*LL*DD];   // modulated q
__device__ float g_att[BB*LL*HS];     // [B,L,H*D]

// ------------------ bf16 helpers ------------------
__device__ __forceinline__ unsigned pack2bf(__nv_bfloat16 a, __nv_bfloat16 b) {
    __nv_bfloat162 t; t.x = a; t.y = b;
    return reinterpret_cast<unsigned&>(t);
}

// split two floats into packed bf16 hi pair + bf16 lo pair (k-adjacent: x0 low half)
__device__ __forceinline__ void bsplit2(float x0, float x1, unsigned &hi, unsigned &lo) {
    __nv_bfloat16 h0 = __float2bfloat16(x0);
    __nv_bfloat16 h1 = __float2bfloat16(x1);
    __nv_bfloat16 l0 = __float2bfloat16(x0 - __bfloat162float(h0));
    __nv_bfloat16 l1 = __float2bfloat16(x1 - __bfloat162float(h1));
    hi = pack2bf(h0, h1);
    lo = pack2bf(l0, l1);
}

__device__ __forceinline__ void mma_bf16(float d[4],
                                         unsigned a0, unsigned a1, unsigned a2, unsigned a3,
                                         unsigned b0, unsigned b1)
{
    asm volatile(
        "mma.sync.aligned.m16n8k16.row.col.f32.bf16.bf16.f32 "
        "{%0,%1,%2,%3}, {%4,%5,%6,%7}, {%8,%9}, {%0,%1,%2,%3};\n"
        : "+f"(d[0]), "+f"(d[1]), "+f"(d[2]), "+f"(d[3])
        : "r"(a0), "r"(a1), "r"(a2), "r"(a3), "r"(b0), "r"(b1));
}

// ====================================================================
// bf16 tensor-core GEMM with 3-term compensation, 2-stage smem pipeline:
//   C[M,N] = A[M,K] @ Bw[N,K]^T   (both K-contiguous, fp32 in/out)
// Block tile 128x128, BK=32, 256 threads (8 warps 2x4), warp tile 64x32.
// One __syncthreads per K-iter (double-buffered smem stages).
// ====================================================================
#define BP 40                  // bf16 pitch
#define GST (4*128*BP)         // bf16 elems per stage (AsHi,AsLo,BsHi,BsLo)

template<int OUTMODE>
__global__ void __launch_bounds__(256, 1) gemm_bf16(const float* __restrict__ A,
                                                    const float* __restrict__ Bw,
                                                    float* __restrict__ C,
                                                    int M, int N, int K)
{
    extern __shared__ float smf[];
    __nv_bfloat16* smb = (__nv_bfloat16*)smf;

    const int tid  = threadIdx.x;
    const int br   = blockIdx.y;
    const int bc   = blockIdx.x;
    const int wid  = tid >> 5;
    const int lane = tid & 31;
    const int g    = lane >> 2;
    const int tig  = lane & 3;

    const int wm = wid >> 2;
    const int wn = wid & 3;

    const float* Ab = A  + (long)br * 128 * K;
    const float* Bb = Bw + (long)bc * 128 * K;

    float acc[4][4][4];
#pragma unroll
    for (int mt = 0; mt < 4; ++mt)
#pragma unroll
        for (int nt = 0; nt < 4; ++nt)
#pragma unroll
            for (int r = 0; r < 4; ++r) acc[mt][nt][r] = 0.f;

    const int ldrow = tid >> 3;          // 0..31 (advance by 32)
    const int ldkq  = tid & 7;           // float4 slot (k = ldkq*4..+3)

    auto store_tile = [&](int s, const float4* av, const float4* bv) {
        __nv_bfloat16* AsHi = smb + s * GST;
        __nv_bfloat16* AsLo = AsHi + 128 * BP;
        __nv_bfloat16* BsHi = AsLo + 128 * BP;
        __nv_bfloat16* BsLo = BsHi + 128 * BP;
#pragma unroll
        for (int it = 0; it < 4; ++it) {
            int row = ldrow + it * 32;
            float4 a = av[it];
            unsigned h01, l01, h23, l23;
            bsplit2(a.x, a.y, h01, l01);
            bsplit2(a.z, a.w, h23, l23);
            *(uint2*)(AsHi + row * BP + ldkq * 4) = make_uint2(h01, h23);
            *(uint2*)(AsLo + row * BP + ldkq * 4) = make_uint2(l01, l23);
            float4 b = bv[it];
            bsplit2(b.x, b.y, h01, l01);
            bsplit2(b.z, b.w, h23, l23);
            *(uint2*)(BsHi + row * BP + ldkq * 4) = make_uint2(h01, h23);
            *(uint2*)(BsLo + row * BP + ldkq * 4) = make_uint2(l01, l23);
        }
    };

    float4 pfA[4], pfB[4];
#pragma unroll
    for (int it = 0; it < 4; ++it) {
        int row = ldrow + it * 32;
        pfA[it] = *(const float4*)(Ab + (long)row * K + ldkq * 4);
        pfB[it] = *(const float4*)(Bb + (long)row * K + ldkq * 4);
    }
    store_tile(0, pfA, pfB);
    __syncthreads();

    const int nKt = K / 32;
    for (int kt = 0; kt < nKt; ++kt) {
        const int s = kt & 1;
        if (kt + 1 < nKt) {
            int k0 = (kt + 1) * 32;
#pragma unroll
            for (int it = 0; it < 4; ++it) {
                int row = ldrow + it * 32;
                pfA[it] = *(const float4*)(Ab + (long)row * K + k0 + ldkq * 4);
                pfB[it] = *(const float4*)(Bb + (long)row * K + k0 + ldkq * 4);
            }
        }

        const __nv_bfloat16* AsHi = smb + s * GST;
        const __nv_bfloat16* AsLo = AsHi + 128 * BP;
        const __nv_bfloat16* BsHi = AsLo + 128 * BP;
        const __nv_bfloat16* BsLo = BsHi + 128 * BP;

        // 2 k-steps of 16
#pragma unroll
        for (int ks = 0; ks < 2; ++ks) {
            const int kk = ks * 16;
            unsigned ah[4][4], al[4][4];
#pragma unroll
            for (int mt = 0; mt < 4; ++mt) {
                int m = wm * 64 + mt * 16 + g;
                const __nv_bfloat16* pH = AsHi + m * BP + kk + tig * 2;
                const __nv_bfloat16* pL = AsLo + m * BP + kk + tig * 2;
                ah[mt][0] = *(const unsigned*)(pH);
                ah[mt][1] = *(const unsigned*)(pH + 8 * BP);
                ah[mt][2] = *(const unsigned*)(pH + 8);
                ah[mt][3] = *(const unsigned*)(pH + 8 * BP + 8);
                al[mt][0] = *(const unsigned*)(pL);
                al[mt][1] = *(const unsigned*)(pL + 8 * BP);
                al[mt][2] = *(const unsigned*)(pL + 8);
                al[mt][3] = *(const unsigned*)(pL + 8 * BP + 8);
            }
            unsigned bh[4][2], bl[4][2];
#pragma unroll
            for (int nt = 0; nt < 4; ++nt) {
                int n = wn * 32 + nt * 8 + g;
                const __nv_bfloat16* pH = BsHi + n * BP + kk + tig * 2;
                const __nv_bfloat16* pL = BsLo + n * BP + kk + tig * 2;
                bh[nt][0] = *(const unsigned*)(pH);
                bh[nt][1] = *(const unsigned*)(pH + 8);
                bl[nt][0] = *(const unsigned*)(pL);
                bl[nt][1] = *(const unsigned*)(pL + 8);
            }
#pragma unroll
            for (int mt = 0; mt < 4; ++mt) {
#pragma unroll
                for (int nt = 0; nt < 4; ++nt) {
                    mma_bf16(acc[mt][nt], ah[mt][0], ah[mt][1], ah[mt][2], ah[mt][3],
                             bh[nt][0], bh[nt][1]);
                    mma_bf16(acc[mt][nt], al[mt][0], al[mt][1], al[mt][2], al[mt][3],
                             bh[nt][0], bh[nt][1]);
                    mma_bf16(acc[mt][nt], ah[mt][0], ah[mt][1], ah[mt][2], ah[mt][3],
                             bl[nt][0], bl[nt][1]);
                }
            }
        }
        if (kt + 1 < nKt) {
            store_tile(s ^ 1, pfA, pfB);
        }
        __syncthreads();
    }

#pragma unroll
    for (int mt = 0; mt < 4; ++mt) {
#pragma unroll
        for (int nt = 0; nt < 4; ++nt) {
            int jj = bc * 128 + wn * 32 + nt * 8 + tig * 2;
#pragma unroll
            for (int half = 0; half < 2; ++half) {
                int ii = br * 128 + wm * 64 + mt * 16 + g + half * 8;
                float2 val;
                val.x = acc[mt][nt][half * 2 + 0];
                val.y = acc[mt][nt][half * 2 + 1];
                if (OUTMODE == 0) {
                    *(float2*)(C + (long)ii * N + jj) = val;
                } else {
                    int b = ii >> 9, l = ii & 511;
                    int h = jj >> 6, d = jj & 63;
                    *(float2*)(C + (((long)(b * 16 + h) * 512) + l) * 64 + d) = val;
                }
            }
        }
    }
}

// ====================================================================
// Tensor-core flash attention, all-bf16 3-term.
// S = QK^T: bf16 m16n8k16 (K tile d-contiguous, packed frags).
// PV: bf16 m16n8k16 — V stored TRANSPOSED in smem as packed j-pair bf16
//     (Vt[d][jp], pitch 36 words -> frag bank 4g+tig all-distinct),
//     P written by softmax directly as packed bf16 hi/lo (pitch 36 words).
// BM=128 q rows, 8 warps (m16 strip each), KV tiles of 64. Softmax warp-local.
// ====================================================================
#define KP  72   // bf16 pitch for K tiles
#define VTP 36   // unsigned pitch for transposed V (packed j-pairs)
#define PP  36   // unsigned pitch for P (packed j-pairs)
#define QSP 68   // fp32 pitch for Q staging
// smem float offsets
#define OFF_KHI 0                         // bf16 KHi: 64*72 = 2304 floats
#define OFF_KLO 2304
#define OFF_VTH 4608                      // unsigned VtHi: 64*36 = 2304
#define OFF_VTL 6912
#define OFF_PQ  9216                      // Q stage (128*68=8704f) aliased with PH+PL (2*4608)
#define OFF_MS  18432                     // mask bytes: 128*64 = 2048 floats
#define ATTN_SMEM_FLOATS 20480            // 81920 B

__global__ void __launch_bounds__(256, 1) attn_tc(
    const float* __restrict__ Q,
    const float* __restrict__ Kb, long kBS, long kHS, int kRS,
    const float* __restrict__ Vb, long vBS, long vHS, int vRS,
    const unsigned int* __restrict__ mask,
    float* __restrict__ Ob, long oBS, long oHS, int oRS,
    int residual)
{
    extern __shared__ float sm[];
    __nv_bfloat16* Khi = (__nv_bfloat16*)(sm + OFF_KHI);
    __nv_bfloat16* Klo = (__nv_bfloat16*)(sm + OFF_KLO);
    unsigned* VtHi = (unsigned*)(sm + OFF_VTH);
    unsigned* VtLo = (unsigned*)(sm + OFF_VTL);
    float*    Qs   = sm + OFF_PQ;                 // staging only (pre-loop)
    unsigned* PH   = (unsigned*)(sm + OFF_PQ);    // aliases Qs after frag extract
    unsigned* PL   = PH + 128 * PP;
    unsigned char* Ms = (unsigned char*)(sm + OFF_MS);

    const int b  = blockIdx.z;
    const int h  = blockIdx.y;
    const int q0 = blockIdx.x * 128;

    const float* Qp = Q + (((long)(b*16 + h) * 512) + q0) * 64;
    const float* Kp = Kb + (long)b * kBS + (long)h * kHS;
    const float* Vp = Vb + (long)b * vBS + (long)h * vHS;
    const unsigned int* Mp = mask + (long)b * LL * LL + (long)q0 * LL;
    float* Op = Ob + (long)b * oBS + (long)h * oHS + (long)q0 * oRS;

    const int tid  = threadIdx.x;
    const int w    = tid >> 5;
    const int lane = tid & 31;
    const int g    = lane >> 2;    // 0..7
    const int tig  = lane & 3;     // 0..3
    const int r0   = w * 16 + g;   // block-local q row (also r0+8)

    // ---- stage Q, extract bf16 hi/lo fragments into registers ----
#pragma unroll
    for (int it = 0; it < 8; ++it) {
        int f = tid + it * 256;          // 0..2047 float4
        int row = f >> 4, c4 = f & 15;
        float4 v = *(const float4*)(Qp + (long)row * 64 + c4 * 4);
        float* dst = Qs + row * QSP + c4 * 4;
        dst[0] = v.x; dst[1] = v.y; dst[2] = v.z; dst[3] = v.w;
    }
    __syncthreads();

    unsigned qh[4][4], ql[4][4];   // 4 k16-chunks, 4 packed regs each
#pragma unroll
    for (int kc = 0; kc < 4; ++kc) {
        const float* p0 = Qs + (r0)     * QSP + kc * 16 + tig * 2;
        const float* p1 = Qs + (r0 + 8) * QSP + kc * 16 + tig * 2;
        bsplit2(p0[0], p0[1], qh[kc][0], ql[kc][0]);
        bsplit2(p1[0], p1[1], qh[kc][1], ql[kc][1]);
        bsplit2(p0[8], p0[9], qh[kc][2], ql[kc][2]);
        bsplit2(p1[8], p1[9], qh[kc][3], ql[kc][3]);
    }
    // NOTE: Qs memory is reused as PH/PL inside the loop. All warps have read
    // their Q fragments before the first PH write (separated by the
    // __syncthreads after the first K/V/mask load below).

    float oacc[8][4];
#pragma unroll
    for (int nt = 0; nt < 8; ++nt)
#pragma unroll
        for (int i = 0; i < 4; ++i) oacc[nt][i] = 0.f;

    float m0 = -1e30f, m1 = -1e30f, l0 = 0.f, l1 = 0.f;

    for (int kt = 0; kt < 8; ++kt) {
        const int k0 = kt * 64;

        // ---- load K (bf16 hi/lo, row-major) ----
#pragma unroll
        for (int it = 0; it < 4; ++it) {
            int f = tid + it * 256;      // 0..1023
            int row = f >> 4, c4 = f & 15;
            float4 kv = *(const float4*)(Kp + (long)(k0 + row) * kRS + c4 * 4);
            unsigned h01, l01, h23, l23;
            bsplit2(kv.x, kv.y, h01, l01);
            bsplit2(kv.z, kv.w, h23, l23);
            *(uint2*)(Khi + row * KP + c4 * 4) = make_uint2(h01, h23);
            *(uint2*)(Klo + row * KP + c4 * 4) = make_uint2(l01, l23);
        }
        // ---- load V transposed: Vt[d][jp] = pack(V[2jp][d], V[2jp+1][d]) ----
#pragma unroll
        for (int it = 0; it < 2; ++it) {
            int idx = tid + it * 256;    // 0..511
            int jp = idx & 31;           // j-pair index
            int c4 = idx >> 5;           // 0..15 -> d base c4*4
            const float* v0 = Vp + (long)(k0 + 2 * jp) * vRS + c4 * 4;
            float4 a = *(const float4*)v0;
            float4 bq = *(const float4*)(v0 + vRS);
            unsigned hh, ll;
            bsplit2(a.x, bq.x, hh, ll);
            VtHi[(c4 * 4 + 0) * VTP + jp] = hh; VtLo[(c4 * 4 + 0) * VTP + jp] = ll;
            bsplit2(a.y, bq.y, hh, ll);
            VtHi[(c4 * 4 + 1) * VTP + jp] = hh; VtLo[(c4 * 4 + 1) * VTP + jp] = ll;
            bsplit2(a.z, bq.z, hh, ll);
            VtHi[(c4 * 4 + 2) * VTP + jp] = hh; VtLo[(c4 * 4 + 2) * VTP + jp] = ll;
            bsplit2(a.w, bq.w, hh, ll);
            VtHi[(c4 * 4 + 3) * VTP + jp] = hh; VtLo[(c4 * 4 + 3) * VTP + jp] = ll;
        }
        // ---- mask tile ----
#pragma unroll
        for (int it = 0; it < 8; ++it) {
            int u = tid + it * 256;      // 0..2047
            int row = u >> 4, c4 = u & 15;
            uint4 m4 = *(const uint4*)(Mp + (long)row * LL + k0 + c4 * 4);
            uchar4 pk;
            pk.x = m4.x ? 1 : 0;
            pk.y = m4.y ? 1 : 0;
            pk.z = m4.z ? 1 : 0;
            pk.w = m4.w ? 1 : 0;
            ((uchar4*)Ms)[row * 16 + c4] = pk;
        }
        __syncthreads();

        // ---- S = Q K^T (3-term bf16, k16) ----
        float sacc[8][4];
#pragma unroll
        for (int nt = 0; nt < 8; ++nt) {
#pragma unroll
            for (int i = 0; i < 4; ++i) sacc[nt][i] = 0.f;
#pragma unroll
            for (int kc = 0; kc < 4; ++kc) {
                const __nv_bfloat16* pH = Khi + (nt * 8 + g) * KP + kc * 16 + tig * 2;
                const __nv_bfloat16* pL = Klo + (nt * 8 + g) * KP + kc * 16 + tig * 2;
                unsigned bh0 = *(const unsigned*)(pH);
                unsigned bh1 = *(const unsigned*)(pH + 8);
                unsigned bl0 = *(const unsigned*)(pL);
                unsigned bl1 = *(const unsigned*)(pL + 8);
                mma_bf16(sacc[nt], qh[kc][0], qh[kc][1], qh[kc][2], qh[kc][3], bh0, bh1);
                mma_bf16(sacc[nt], ql[kc][0], ql[kc][1], ql[kc][2], ql[kc][3], bh0, bh1);
                mma_bf16(sacc[nt], qh[kc][0], qh[kc][1], qh[kc][2], qh[kc][3], bl0, bl1);
            }
        }

        // ---- scale + mask ----
#pragma unroll
        for (int nt = 0; nt < 8; ++nt) {
            uchar2 mA = *(const uchar2*)(Ms + (r0)     * 64 + nt * 8 + tig * 2);
            uchar2 mB = *(const uchar2*)(Ms + (r0 + 8) * 64 + nt * 8 + tig * 2);
            sacc[nt][0] = mA.x ? -1e9f : sacc[nt][0] * 0.125f;
            sacc[nt][1] = mA.y ? -1e9f : sacc[nt][1] * 0.125f;
            sacc[nt][2] = mB.x ? -1e9f : sacc[nt][2] * 0.125f;
            sacc[nt][3] = mB.y ? -1e9f : sacc[nt][3] * 0.125f;
        }

        // ---- online softmax (warp-local, quad reductions) ----
        float mx0 = -3.0e38f, mx1 = -3.0e38f;
#pragma unroll
        for (int nt = 0; nt < 8; ++nt) {
            mx0 = fmaxf(mx0, fmaxf(sacc[nt][0], sacc[nt][1]));
            mx1 = fmaxf(mx1, fmaxf(sacc[nt][2], sacc[nt][3]));
        }
        mx0 = fmaxf(mx0, __shfl_xor_sync(0xffffffffu, mx0, 1));
        mx0 = fmaxf(mx0, __shfl_xor_sync(0xffffffffu, mx0, 2));
        mx1 = fmaxf(mx1, __shfl_xor_sync(0xffffffffu, mx1, 1));
        mx1 = fmaxf(mx1, __shfl_xor_sync(0xffffffffu, mx1, 2));

        float mn0 = fmaxf(m0, mx0), mn1 = fmaxf(m1, mx1);
        float al0 = __expf(m0 - mn0), al1 = __expf(m1 - mn1);
        m0 = mn0; m1 = mn1;

        float sum0 = 0.f, sum1 = 0.f;
#pragma unroll
        for (int nt = 0; nt < 8; ++nt) {
            float p00 = __expf(sacc[nt][0] - m0);
            float p01 = __expf(sacc[nt][1] - m0);
            float p10 = __expf(sacc[nt][2] - m1);
            float p11 = __expf(sacc[nt][3] - m1);
            sum0 += p00 + p01;
            sum1 += p10 + p11;
            unsigned hh, ll;
            bsplit2(p00, p01, hh, ll);
            PH[(r0)     * PP + nt * 4 + tig] = hh;
            PL[(r0)     * PP + nt * 4 + tig] = ll;
            bsplit2(p10, p11, hh, ll);
            PH[(r0 + 8) * PP + nt * 4 + tig] = hh;
            PL[(r0 + 8) * PP + nt * 4 + tig] = ll;
        }
        sum0 += __shfl_xor_sync(0xffffffffu, sum0, 1);
        sum0 += __shfl_xor_sync(0xffffffffu, sum0, 2);
        sum1 += __shfl_xor_sync(0xffffffffu, sum1, 1);
        sum1 += __shfl_xor_sync(0xffffffffu, sum1, 2);
        l0 = l0 * al0 + sum0;
        l1 = l1 * al1 + sum1;

#pragma unroll
        for (int nt = 0; nt < 8; ++nt) {
            oacc[nt][0] *= al0; oacc[nt][1] *= al0;
            oacc[nt][2] *= al1; oacc[nt][3] *= al1;
        }
        __syncwarp();

        // ---- O += P V (3-term bf16, k16) ----
#pragma unroll
        for (int kc = 0; kc < 4; ++kc) {
            const unsigned* pHr0 = PH + (r0)     * PP + kc * 8 + tig;
            const unsigned* pHr8 = PH + (r0 + 8) * PP + kc * 8 + tig;
            const unsigned* pLr0 = PL + (r0)     * PP + kc * 8 + tig;
            const unsigned* pLr8 = PL + (r0 + 8) * PP + kc * 8 + tig;
            unsigned ph0 = pHr0[0], ph1 = pHr8[0], ph2 = pHr0[4], ph3 = pHr8[4];
            unsigned pl0 = pLr0[0], pl1 = pLr8[0], pl2 = pLr0[4], pl3 = pLr8[4];
#pragma unroll
            for (int nt = 0; nt < 8; ++nt) {
                const unsigned* vH = VtHi + (nt * 8 + g) * VTP + kc * 8 + tig;
                const unsigned* vL = VtLo + (nt * 8 + g) * VTP + kc * 8 + tig;
                unsigned bh0 = vH[0], bh1 = vH[4];
                unsigned bl0 = vL[0], bl1 = vL[4];
                mma_bf16(oacc[nt], ph0, ph1, ph2, ph3, bh0, bh1);
                mma_bf16(oacc[nt], pl0, pl1, pl2, pl3, bh0, bh1);
                mma_bf16(oacc[nt], ph0, ph1, ph2, ph3, bl0, bl1);
            }
        }
        __syncthreads();
    }

    // ---- finalize: /l, residual (from global Q), store ----
    float inv0 = 1.0f / l0, inv1 = 1.0f / l1;
#pragma unroll
    for (int nt = 0; nt < 8; ++nt) {
        int c = nt * 8 + tig * 2;
        float2 v0 = make_float2(oacc[nt][0] * inv0, oacc[nt][1] * inv0);
        float2 v1 = make_float2(oacc[nt][2] * inv1, oacc[nt][3] * inv1);
        if (residual) {
            float2 qres0 = *(const float2*)(Qp + (long)(r0)     * 64 + c);
            float2 qres1 = *(const float2*)(Qp + (long)(r0 + 8) * 64 + c);
            v0.x += qres0.x; v0.y += qres0.y;
            v1.x += qres1.x; v1.y += qres1.y;
        }
        *(float2*)(Op + (long)(r0)     * oRS + c) = v0;
        *(float2*)(Op + (long)(r0 + 8) * oRS + c) = v1;
    }
}

// ====================================================================
extern "C" void kernel_launch(void* const* d_in, const int* in_sizes, int n_in,
                              void* d_out, int out_size)
{
    (void)in_sizes; (void)n_in; (void)out_size;
    const float* v   = (const float*)d_in[0];
    const float* k   = (const float*)d_in[1];
    const float* q   = (const float*)d_in[2];
    const float* img = (const float*)d_in[3];
    const float* Wv  = (const float*)d_in[4];
    const float* Wk  = (const float*)d_in[5];
    const float* Wq  = (const float*)d_in[6];
    const float* Wm  = (const float*)d_in[7];
    const unsigned int* absm = (const unsigned int*)d_in[8];
    const unsigned int* mask = (const unsigned int*)d_in[9];
    float* out = (float*)d_out;

    float *vh, *kh, *qh, *qn, *att;
    cudaGetSymbolAddress((void**)&vh,  g_vh);
    cudaGetSymbolAddress((void**)&kh,  g_kh);
    cudaGetSymbolAddress((void**)&qh,  g_qh);
    cudaGetSymbolAddress((void**)&qn,  g_qn);
    cudaGetSymbolAddress((void**)&att, g_att);

    const int gsmem = 2 * GST * (int)sizeof(__nv_bfloat16);   // 81920
    cudaFuncSetAttribute(gemm_bf16<0>,
                         cudaFuncAttributeMaxDynamicSharedMemorySize, gsmem);
    cudaFuncSetAttribute(gemm_bf16<1>,
                         cudaFuncAttributeMaxDynamicSharedMemorySize, gsmem);

    dim3 gg(HS / 128, MROWS / 128);   // (8, 64)
    gemm_bf16<1><<<gg, 256, gsmem>>>(v, Wv, vh, MROWS, HS, HS);
    gemm_bf16<1><<<gg, 256, gsmem>>>(k, Wk, kh, MROWS, HS, HS);
    gemm_bf16<1><<<gg, 256, gsmem>>>(q, Wq, qh, MROWS, HS, HS);

    const int asmem = ATTN_SMEM_FLOATS * (int)sizeof(float);   // 81920
    cudaFuncSetAttribute(attn_tc,
                         cudaFuncAttributeMaxDynamicSharedMemorySize, asmem);

    dim3 ga(LL / 128, HH, BB);   // (4, 16, 16)
    // Stage 1: modulate — K=V=img_abs (strided heads), residual, out -> g_qn [B,H,L,D]
    attn_tc<<<ga, 256, asmem>>>(
        qh,
        img, (long)LL * HS, 64L, HS,
        img, (long)LL * HS, 64L, HS,
        absm,
        qn,  (long)HH * LL * DD, (long)LL * DD, DD,
        1);
    // Stage 2: main attention — K=kh, V=vh, out -> g_att [B,L,H*D]
    attn_tc<<<ga, 256, asmem>>>(
        qn,
        kh, (long)HH * LL * DD, (long)LL * DD, DD,
        vh, (long)HH * LL * DD, (long)LL * DD, DD,
        mask,
        att, (long)LL * HS, 64L, HS,
        0);

    gemm_bf16<0><<<gg, 256, gsmem>>>(att, Wm, out, MROWS, HS, HS);
}